// round 13
// baseline (speedup 1.0000x reference)
#include <cuda_runtime.h>
#include <cuda_bf16.h>
#include <cuda_fp8.h>
#include <stdint.h>
#include <math.h>

// ---------------------------------------------------------------------------
// MultiModalAttention (sm_103 base target).
// Round 13: main term bf16 HMMA (Ah x Wh*2^12) + cross terms in FP8 e4m3
// m16n8k32 (e4m3(Ah) x e4m3(Wl*2^12)  and  e4m3(Al*2^9) x e4m3(Wh*2^3)).
// All three products share ONE fp32 accumulator at scale 2^12; epilogue
// multiplies by 2^-12. Same R6/R10 pipeline skeleton (512 thr, BM=256 BN=128
// BK=32, 3 stages, 1 sync/ktile).
// ---------------------------------------------------------------------------

#define BATCH   8192
#define IMGDIM  2048
#define QDIM    768
#define HDIM    1024
#define H3      3072
#define B2      16384
#define NHEADS  16
#define HD      64

#define BM 256
#define BN 128
#define BK 32
#define KSB 80                     // bf16 row stride (64B data + 16 pad)
#define KS8 48                     // fp8  row stride (32B data + 16 pad)
#define ARR_AH (BM * KSB)          // 20480
#define ARR_A8 (BM * KS8)          // 12288
#define ARR_BH (BN * KSB)          // 10240
#define ARR_B8 (BN * KS8)          // 6144
#define OFF_AH  0
#define OFF_A8H (ARR_AH)                   // 20480
#define OFF_A8L (OFF_A8H + ARR_A8)         // 32768
#define OFF_BH  (OFF_A8L + ARR_A8)         // 45056
#define OFF_B8H (OFF_BH + ARR_BH)          // 55296
#define OFF_B8L (OFF_B8H + ARR_B8)         // 61440
#define STAGE_BYTES (OFF_B8L + ARR_B8)     // 67584
#define NSTAGE 3
#define SMEM_BYTES (NSTAGE * STAGE_BYTES)  // 202752

#define INV_SCALE (1.0f / 4096.0f)

// ---------------- device scratch ---------------------------------------------
__device__ float g_qkv[(size_t)B2 * H3];
__device__ float g_o2 [(size_t)B2 * HDIM];

__device__ __nv_bfloat16 g_f1h[(size_t)BATCH * IMGDIM];
__device__ __nv_bfloat16 g_f2h[(size_t)BATCH * QDIM];
__device__ uint8_t g_f18h[(size_t)BATCH * IMGDIM], g_f18l[(size_t)BATCH * IMGDIM];
__device__ uint8_t g_f28h[(size_t)BATCH * QDIM],  g_f28l[(size_t)BATCH * QDIM];

__device__ __nv_bfloat16 g_xh[(size_t)B2 * HDIM], g_xl[(size_t)B2 * HDIM];
__device__ uint8_t g_x8h[(size_t)B2 * HDIM], g_x8l[(size_t)B2 * HDIM];

__device__ __nv_bfloat16 g_ah[(size_t)B2 * HDIM];
__device__ uint8_t g_a8h[(size_t)B2 * HDIM], g_a8l[(size_t)B2 * HDIM];

// weights: bf16 = wh*2^12; fp8 hi = e4m3(wh*2^3); fp8 lo = e4m3(wl*2^12)
__device__ __nv_bfloat16 g_w1h[(size_t)HDIM * IMGDIM];
__device__ uint8_t g_w18h[(size_t)HDIM * IMGDIM], g_w18l[(size_t)HDIM * IMGDIM];
__device__ __nv_bfloat16 g_w2h[(size_t)HDIM * QDIM];
__device__ uint8_t g_w28h[(size_t)HDIM * QDIM], g_w28l[(size_t)HDIM * QDIM];
__device__ __nv_bfloat16 g_wqh[(size_t)H3 * HDIM];
__device__ uint8_t g_wq8h[(size_t)H3 * HDIM], g_wq8l[(size_t)H3 * HDIM];
__device__ __nv_bfloat16 g_woh[(size_t)HDIM * HDIM];
__device__ uint8_t g_wo8h[(size_t)HDIM * HDIM], g_wo8l[(size_t)HDIM * HDIM];

// ---------------- helpers ------------------------------------------------------
__device__ __forceinline__ uint32_t smem_u32(const void* p) {
    return (uint32_t)__cvta_generic_to_shared(p);
}
__device__ __forceinline__ void cp16(uint32_t s, const void* g) {
    asm volatile("cp.async.cg.shared.global [%0], [%1], 16;"
                 :: "r"(s), "l"(__cvta_generic_to_global(g)) : "memory");
}
__device__ __forceinline__ unsigned short cvt_e4m3x2(float lo, float hi) {
    return (unsigned short)__nv_cvt_float2_to_fp8x2(
        make_float2(lo, hi), __NV_SATFINITE, __NV_E4M3);
}
#define LDMX4(r, addr) \
    asm volatile("ldmatrix.sync.aligned.m8n8.x4.shared.b16 {%0,%1,%2,%3}, [%4];" \
        : "=r"((r)[0]), "=r"((r)[1]), "=r"((r)[2]), "=r"((r)[3]) : "r"(addr))
#define MMA16816(c, a, b0, b1) \
    asm volatile("mma.sync.aligned.m16n8k16.row.col.f32.bf16.bf16.f32 " \
        "{%0,%1,%2,%3}, {%4,%5,%6,%7}, {%8,%9}, {%0,%1,%2,%3};" \
        : "+f"((c)[0]), "+f"((c)[1]), "+f"((c)[2]), "+f"((c)[3]) \
        : "r"((a)[0]), "r"((a)[1]), "r"((a)[2]), "r"((a)[3]), "r"(b0), "r"(b1))
#define MMAFP8(c, a, b0, b1) \
    asm volatile("mma.sync.aligned.m16n8k32.row.col.f32.e4m3.e4m3.f32 " \
        "{%0,%1,%2,%3}, {%4,%5,%6,%7}, {%8,%9}, {%0,%1,%2,%3};" \
        : "+f"((c)[0]), "+f"((c)[1]), "+f"((c)[2]), "+f"((c)[3]) \
        : "r"((a)[0]), "r"((a)[1]), "r"((a)[2]), "r"((a)[3]), "r"(b0), "r"(b1))

// ---------------- stage loader (512 threads, 6 cp.async each) -----------------
__device__ __forceinline__ void load_stage(
    uint32_t st, int tid,
    const __nv_bfloat16* __restrict__ Ah,
    const uint8_t* __restrict__ A8h, const uint8_t* __restrict__ A8l,
    const __nv_bfloat16* __restrict__ Bh,
    const uint8_t* __restrict__ B8h, const uint8_t* __restrict__ B8l,
    int bm, int bn, int K, int k0)
{
    #pragma unroll
    for (int t = 0; t < 6; t++) {
        const int ci = tid + t * 512;
        const void* g;
        uint32_t sa;
        if (t < 2) {                       // AH bf16: 1024 chunks
            const int row = ci >> 2, q = ci & 3;
            g  = Ah + (size_t)(bm + row) * K + k0 + q * 8;
            sa = st + OFF_AH + (uint32_t)row * KSB + q * 16;
        } else if (t == 2) {               // A8H: 512 chunks
            const int idx = ci - 1024, row = idx >> 1, q = idx & 1;
            g  = A8h + (size_t)(bm + row) * K + k0 + q * 16;
            sa = st + OFF_A8H + (uint32_t)row * KS8 + q * 16;
        } else if (t == 3) {               // A8L
            const int idx = ci - 1536, row = idx >> 1, q = idx & 1;
            g  = A8l + (size_t)(bm + row) * K + k0 + q * 16;
            sa = st + OFF_A8L + (uint32_t)row * KS8 + q * 16;
        } else if (t == 4) {               // BH bf16: 512 chunks
            const int idx = ci - 2048, row = idx >> 2, q = idx & 3;
            g  = Bh + (size_t)(bn + row) * K + k0 + q * 8;
            sa = st + OFF_BH + (uint32_t)row * KSB + q * 16;
        } else {                           // B8H (256) then B8L (256)
            int idx = ci - 2560;
            if (idx < 256) {
                const int row = idx >> 1, q = idx & 1;
                g  = B8h + (size_t)(bn + row) * K + k0 + q * 16;
                sa = st + OFF_B8H + (uint32_t)row * KS8 + q * 16;
            } else {
                idx -= 256;
                const int row = idx >> 1, q = idx & 1;
                g  = B8l + (size_t)(bn + row) * K + k0 + q * 16;
                sa = st + OFF_B8L + (uint32_t)row * KS8 + q * 16;
            }
        }
        cp16(sa, g);
    }
    asm volatile("cp.async.commit_group;" ::: "memory");
}

// ---------------- shared GEMM body ---------------------------------------------
__device__ __forceinline__ void gemm_body(
    const __nv_bfloat16* __restrict__ Ah,
    const uint8_t* __restrict__ A8h, const uint8_t* __restrict__ A8l,
    const __nv_bfloat16* __restrict__ Bh,
    const uint8_t* __restrict__ B8h, const uint8_t* __restrict__ B8l,
    const float* __restrict__ bias, float* __restrict__ outF,
    __nv_bfloat16* __restrict__ outH, __nv_bfloat16* __restrict__ outL,
    uint8_t* __restrict__ out8H, uint8_t* __restrict__ out8L,
    int N, int K, int row_mul, int row_off, int bm, int bn, uint32_t sb)
{
    const int tid   = threadIdx.x;
    const int wid   = tid >> 5;
    const int lane  = tid & 31;
    const int warpM = wid >> 2;      // 0..3 -> 64 rows each
    const int warpN = wid & 3;       // 0..3 -> 32 cols each

    float c[4][4][4];                // 64 regs, scale 2^12
    #pragma unroll
    for (int i = 0; i < 4; i++)
        #pragma unroll
        for (int j = 0; j < 4; j++)
            #pragma unroll
            for (int k = 0; k < 4; k++) c[i][j][k] = 0.0f;

    const int NT = K / BK;
    load_stage(sb,               tid, Ah, A8h, A8l, Bh, B8h, B8l, bm, bn, K, 0);
    load_stage(sb + STAGE_BYTES, tid, Ah, A8h, A8l, Bh, B8h, B8l, bm, bn, K, BK);

    const int g8 = lane >> 3, lr = lane & 7;
    const int a_row = warpM * 64 + ((g8 & 1) ? 8 : 0) + lr;   // + mt*16
    const int a_kb  = (g8 >> 1) ? 16 : 0;                     // byte offset
    const int b_row = warpN * 32 + ((g8 >> 1) ? 8 : 0) + lr;  // + n16*16
    const int b_kb  = (g8 & 1) ? 16 : 0;

    for (int kt = 0; kt < NT; kt++) {
        if (kt + 1 < NT) asm volatile("cp.async.wait_group 1;" ::: "memory");
        else             asm volatile("cp.async.wait_group 0;" ::: "memory");
        __syncthreads();

        const uint32_t st = sb + (uint32_t)(kt % NSTAGE) * STAGE_BYTES;

        // ---- bf16 main term: Ah x (Wh*2^12) ----
        #pragma unroll
        for (int kk = 0; kk < 2; kk++) {
            const int kb = kk * 32;
            uint32_t ah[4][4];
            #pragma unroll
            for (int mt = 0; mt < 4; mt++)
                LDMX4(ah[mt], st + OFF_AH +
                      (uint32_t)(a_row + mt * 16) * KSB + a_kb + kb);
            #pragma unroll
            for (int n16 = 0; n16 < 2; n16++) {
                uint32_t bh[4];
                LDMX4(bh, st + OFF_BH +
                      (uint32_t)(b_row + n16 * 16) * KSB + b_kb + kb);
                #pragma unroll
                for (int mt = 0; mt < 4; mt++)
                    #pragma unroll
                    for (int nn = 0; nn < 2; nn++)
                        MMA16816(c[mt][n16 * 2 + nn], ah[mt],
                                 bh[2 * nn], bh[2 * nn + 1]);
            }
        }

        // ---- fp8 cross terms (k32 covers whole BK) ----
        {
            uint32_t a8h[4][4], a8l[4][4];
            #pragma unroll
            for (int mt = 0; mt < 4; mt++) {
                const uint32_t aaddr = st + OFF_A8H +
                    (uint32_t)(a_row + mt * 16) * KS8 + a_kb;
                LDMX4(a8h[mt], aaddr);
                LDMX4(a8l[mt], aaddr + (OFF_A8L - OFF_A8H));
            }
            #pragma unroll
            for (int n16 = 0; n16 < 2; n16++) {
                const uint32_t baddr = st + OFF_B8H +
                    (uint32_t)(b_row + n16 * 16) * KS8 + b_kb;
                uint32_t b8h[4], b8l[4];
                LDMX4(b8h, baddr);
                LDMX4(b8l, baddr + (OFF_B8L - OFF_B8H));
                #pragma unroll
                for (int mt = 0; mt < 4; mt++)
                    #pragma unroll
                    for (int nn = 0; nn < 2; nn++)
                        MMAFP8(c[mt][n16 * 2 + nn], a8h[mt],
                               b8l[2 * nn], b8l[2 * nn + 1]);
                #pragma unroll
                for (int mt = 0; mt < 4; mt++)
                    #pragma unroll
                    for (int nn = 0; nn < 2; nn++)
                        MMAFP8(c[mt][n16 * 2 + nn], a8l[mt],
                               b8h[2 * nn], b8h[2 * nn + 1]);
            }
        }

        if (kt + 2 < NT)
            load_stage(sb + (uint32_t)((kt + 2) % NSTAGE) * STAGE_BYTES,
                       tid, Ah, A8h, A8l, Bh, B8h, B8l, bm, bn, K,
                       (kt + 2) * BK);
    }

    // ---- epilogue: unscale 2^-12, bias, store ----
    const int quad = lane >> 2;
    const int tq   = lane & 3;
    #pragma unroll
    for (int nt = 0; nt < 4; nt++) {
        const int col = bn + warpN * 32 + nt * 8 + tq * 2;
        float bv0 = 0.0f, bv1 = 0.0f;
        if (bias) { bv0 = bias[col]; bv1 = bias[col + 1]; }
        #pragma unroll
        for (int mt = 0; mt < 4; mt++) {
            #pragma unroll
            for (int half = 0; half < 2; half++) {
                const int grow = bm + warpM * 64 + mt * 16 + half * 8 + quad;
                const size_t off = ((size_t)grow * row_mul + row_off) * N + col;
                float v0 = c[mt][nt][2 * half + 0] * INV_SCALE + bv0;
                float v1 = c[mt][nt][2 * half + 1] * INV_SCALE + bv1;
                if (outF) *(float2*)(outF + off) = make_float2(v0, v1);
                if (outH) {
                    __nv_bfloat16 h0 = __float2bfloat16(v0);
                    __nv_bfloat16 h1 = __float2bfloat16(v1);
                    float h0f = __bfloat162float(h0);
                    float h1f = __bfloat162float(h1);
                    __nv_bfloat162 hp; hp.x = h0; hp.y = h1;
                    __nv_bfloat162 lp;
                    lp.x = __float2bfloat16(v0 - h0f);
                    lp.y = __float2bfloat16(v1 - h1f);
                    *(__nv_bfloat162*)(outH + off) = hp;
                    *(__nv_bfloat162*)(outL + off) = lp;
                    *(unsigned short*)(out8H + off) = cvt_e4m3x2(h0f, h1f);
                    *(unsigned short*)(out8L + off) =
                        cvt_e4m3x2((v0 - h0f) * 512.0f, (v1 - h1f) * 512.0f);
                }
            }
        }
    }
}

// ---------------- GEMM kernels -------------------------------------------------
__global__ void __launch_bounds__(512, 1)
gemm_hmma(const __nv_bfloat16* __restrict__ Ah,
          const uint8_t* __restrict__ A8h, const uint8_t* __restrict__ A8l,
          const __nv_bfloat16* __restrict__ Bh,
          const uint8_t* __restrict__ B8h, const uint8_t* __restrict__ B8l,
          const float* __restrict__ bias, float* __restrict__ outF,
          int N, int K)
{
    extern __shared__ char smem[];
    gemm_body(Ah, A8h, A8l, Bh, B8h, B8l, bias, outF,
              nullptr, nullptr, nullptr, nullptr,
              N, K, 1, 0, blockIdx.y * BM, blockIdx.x * BN, smem_u32(smem));
}

__global__ void __launch_bounds__(512, 1)
gemm_proj(const __nv_bfloat16* __restrict__ f1h,
          const uint8_t* __restrict__ f18h, const uint8_t* __restrict__ f18l,
          const __nv_bfloat16* __restrict__ w1h,
          const uint8_t* __restrict__ w18h, const uint8_t* __restrict__ w18l,
          const float* __restrict__ b1,
          const __nv_bfloat16* __restrict__ f2h,
          const uint8_t* __restrict__ f28h, const uint8_t* __restrict__ f28l,
          const __nv_bfloat16* __restrict__ w2h,
          const uint8_t* __restrict__ w28h, const uint8_t* __restrict__ w28l,
          const float* __restrict__ b2,
          __nv_bfloat16* __restrict__ xh, __nv_bfloat16* __restrict__ xl,
          uint8_t* __restrict__ x8h, uint8_t* __restrict__ x8l)
{
    extern __shared__ char smem[];
    if (blockIdx.z == 0)
        gemm_body(f1h, f18h, f18l, w1h, w18h, w18l, b1, nullptr,
                  xh, xl, x8h, x8l,
                  HDIM, IMGDIM, 2, 0, blockIdx.y * BM, blockIdx.x * BN,
                  smem_u32(smem));
    else
        gemm_body(f2h, f28h, f28l, w2h, w28h, w28l, b2, nullptr,
                  xh, xl, x8h, x8l,
                  HDIM, QDIM, 2, 1, blockIdx.y * BM, blockIdx.x * BN,
                  smem_u32(smem));
}

// ---------------- activation split: bf16 hi + fp8 hi/lo ------------------------
__global__ void __launch_bounds__(256)
asplit(const float* __restrict__ x, __nv_bfloat16* __restrict__ h,
       uint8_t* __restrict__ h8, uint8_t* __restrict__ l8, size_t n)
{
    size_t i = ((size_t)blockIdx.x * 256 + threadIdx.x) * 4;
    if (i >= n) return;
    float4 v = *(const float4*)(x + i);
    __nv_bfloat16 h0 = __float2bfloat16(v.x), h1 = __float2bfloat16(v.y);
    __nv_bfloat16 h2 = __float2bfloat16(v.z), h3 = __float2bfloat16(v.w);
    float f0 = __bfloat162float(h0), f1 = __bfloat162float(h1);
    float f2 = __bfloat162float(h2), f3 = __bfloat162float(h3);
    __nv_bfloat162 hp0; hp0.x = h0; hp0.y = h1;
    __nv_bfloat162 hp1; hp1.x = h2; hp1.y = h3;
    *(__nv_bfloat162*)(h + i)     = hp0;
    *(__nv_bfloat162*)(h + i + 2) = hp1;
    uint32_t p8h = (uint32_t)cvt_e4m3x2(f0, f1) |
                   ((uint32_t)cvt_e4m3x2(f2, f3) << 16);
    uint32_t p8l = (uint32_t)cvt_e4m3x2((v.x - f0) * 512.0f, (v.y - f1) * 512.0f) |
                   ((uint32_t)cvt_e4m3x2((v.z - f2) * 512.0f, (v.w - f3) * 512.0f) << 16);
    *(uint32_t*)(h8 + i) = p8h;
    *(uint32_t*)(l8 + i) = p8l;
}

// ---------------- weight transpose+split ----------------------------------------
// emits: th = bf16(w)*4096 ; t8h = e4m3(bf16(w)*8) ; t8l = e4m3(wl*4096)
__global__ void __launch_bounds__(256)
wsplit_v2(const float* __restrict__ W1, const float* __restrict__ W2,
          const float* __restrict__ Wq, const float* __restrict__ Wo,
          __nv_bfloat16* __restrict__ w1h, uint8_t* __restrict__ w18h,
          uint8_t* __restrict__ w18l,
          __nv_bfloat16* __restrict__ w2h, uint8_t* __restrict__ w28h,
          uint8_t* __restrict__ w28l,
          __nv_bfloat16* __restrict__ wqh, uint8_t* __restrict__ wq8h,
          uint8_t* __restrict__ wq8l,
          __nv_bfloat16* __restrict__ woh, uint8_t* __restrict__ wo8h,
          uint8_t* __restrict__ wo8l,
          int zbase)
{
    const float* W; __nv_bfloat16* th; uint8_t *t8h, *t8l; int K, N;
    switch (blockIdx.z + zbase) {
        case 0: W = W1; th = w1h; t8h = w18h; t8l = w18l; K = IMGDIM; N = HDIM; break;
        case 1: W = W2; th = w2h; t8h = w28h; t8l = w28l; K = QDIM;   N = HDIM; break;
        case 2: W = Wq; th = wqh; t8h = wq8h; t8l = wq8l; K = HDIM;   N = H3;   break;
        default:W = Wo; th = woh; t8h = wo8h; t8l = wo8l; K = HDIM;   N = HDIM; break;
    }
    const int n0 = blockIdx.x * 32, k0 = blockIdx.y * 64;
    if (n0 >= N || k0 >= K) return;

    __shared__ float tile[64][33];
    const int tx = threadIdx.x & 31, ty = threadIdx.x >> 5;
    #pragma unroll
    for (int i = ty; i < 64; i += 8)
        tile[i][tx] = W[(size_t)(k0 + i) * N + n0 + tx];
    __syncthreads();
    #pragma unroll
    for (int i = 0; i < 4; i++) {
        const int nn = ty + i * 8;
        const int n = n0 + nn;
        float v0 = tile[2 * tx + 0][nn];
        float v1 = tile[2 * tx + 1][nn];
        __nv_bfloat16 h0 = __float2bfloat16(v0);
        __nv_bfloat16 h1 = __float2bfloat16(v1);
        float h0f = __bfloat162float(h0), h1f = __bfloat162float(h1);
        __nv_bfloat162 hp;
        hp.x = __float2bfloat16(h0f * 4096.0f);    // exact power-of-2 scale
        hp.y = __float2bfloat16(h1f * 4096.0f);
        const size_t off = (size_t)n * K + k0 + 2 * tx;
        *(__nv_bfloat162*)(th + off) = hp;
        *(unsigned short*)(t8h + off) = cvt_e4m3x2(h0f * 8.0f, h1f * 8.0f);
        *(unsigned short*)(t8l + off) =
            cvt_e4m3x2((v0 - h0f) * 4096.0f, (v1 - h1f) * 4096.0f);
    }
}

// ---------------- attention (2x2 per head): bf16 hi + fp8 hi/lo -----------------
__global__ void __launch_bounds__(128)
attn_kernel(const float* __restrict__ qkv, __nv_bfloat16* __restrict__ oh,
            uint8_t* __restrict__ o8h, uint8_t* __restrict__ o8l)
{
    const int b = blockIdx.x;
    const int warp = threadIdx.x >> 5;
    const int lane = threadIdx.x & 31;
    const float scale = 0.125f;
    const size_t base0 = (size_t)(2 * b) * H3;
    const size_t base1 = base0 + H3;

    #pragma unroll
    for (int h = warp; h < NHEADS; h += 4) {
        const int off = h * HD + lane;
        float q0a = qkv[base0 + off],          q0b = qkv[base0 + off + 32];
        float k0a = qkv[base0 + HDIM + off],   k0b = qkv[base0 + HDIM + off + 32];
        float v0a = qkv[base0 + 2*HDIM + off], v0b = qkv[base0 + 2*HDIM + off + 32];
        float q1a = qkv[base1 + off],          q1b = qkv[base1 + off + 32];
        float k1a = qkv[base1 + HDIM + off],   k1b = qkv[base1 + HDIM + off + 32];
        float v1a = qkv[base1 + 2*HDIM + off], v1b = qkv[base1 + 2*HDIM + off + 32];

        float s00 = q0a * k0a + q0b * k0b;
        float s01 = q0a * k1a + q0b * k1b;
        float s10 = q1a * k0a + q1b * k0b;
        float s11 = q1a * k1a + q1b * k1b;
        #pragma unroll
        for (int d = 16; d; d >>= 1) {
            s00 += __shfl_xor_sync(0xffffffffu, s00, d);
            s01 += __shfl_xor_sync(0xffffffffu, s01, d);
            s10 += __shfl_xor_sync(0xffffffffu, s10, d);
            s11 += __shfl_xor_sync(0xffffffffu, s11, d);
        }
        s00 *= scale; s01 *= scale; s10 *= scale; s11 *= scale;

        float m0 = fmaxf(s00, s01), m1 = fmaxf(s10, s11);
        float e00 = __expf(s00 - m0), e01 = __expf(s01 - m0);
        float e10 = __expf(s10 - m1), e11 = __expf(s11 - m1);
        float inv0 = 1.0f / (e00 + e01), inv1 = 1.0f / (e10 + e11);
        float p00 = e00 * inv0, p01 = e01 * inv0;
        float p10 = e10 * inv1, p11 = e11 * inv1;

        float r0 = p00 * v0a + p01 * v1a;
        float r1 = p00 * v0b + p01 * v1b;
        float r2 = p10 * v0a + p11 * v1a;
        float r3 = p10 * v0b + p11 * v1b;

        size_t o0 = (size_t)(2 * b) * HDIM + h * HD + lane;
        size_t o1 = o0 + HDIM;
        float rr[4] = {r0, r1, r2, r3};
        size_t oo[4] = {o0, o0 + 32, o1, o1 + 32};
        #pragma unroll
        for (int j = 0; j < 4; j++) {
            __nv_bfloat16 hb = __float2bfloat16(rr[j]);
            float hf = __bfloat162float(hb);
            oh[oo[j]] = hb;
            __nv_fp8_e4m3 e8h(hf);
            __nv_fp8_e4m3 e8l((rr[j] - hf) * 512.0f);
            o8h[oo[j]] = *(uint8_t*)&e8h;
            o8l[oo[j]] = *(uint8_t*)&e8l;
        }
    }
}

// ---------------- LayerNorm(2048) + residual(hi+lo), vectorized ----------------
__global__ void __launch_bounds__(256)
ln_kernel(const float* __restrict__ o2,
          const __nv_bfloat16* __restrict__ xh, const __nv_bfloat16* __restrict__ xl,
          const float* __restrict__ gamma, const float* __restrict__ beta,
          float* __restrict__ out)
{
    const int b = blockIdx.x;
    const int tid = threadIdx.x;
    const float4* x4 = (const float4*)(o2 + (size_t)b * 2048);

    float4 vals[2];
    float sum = 0.0f, sq = 0.0f;
    #pragma unroll
    for (int j = 0; j < 2; j++) {
        float4 v = x4[tid + j * 256];
        vals[j] = v;
        sum += v.x + v.y + v.z + v.w;
        sq  += v.x * v.x + v.y * v.y + v.z * v.z + v.w * v.w;
    }
    #pragma unroll
    for (int d = 16; d; d >>= 1) {
        sum += __shfl_xor_sync(0xffffffffu, sum, d);
        sq  += __shfl_xor_sync(0xffffffffu, sq, d);
    }
    __shared__ float ssum[8], ssq[8];
    const int warp = tid >> 5, lane = tid & 31;
    if (lane == 0) { ssum[warp] = sum; ssq[warp] = sq; }
    __syncthreads();
    float tsum = 0.0f, tsq = 0.0f;
    #pragma unroll
    for (int w = 0; w < 8; w++) { tsum += ssum[w]; tsq += ssq[w]; }

    const float mu   = tsum * (1.0f / 2048.0f);
    const float var  = tsq * (1.0f / 2048.0f) - mu * mu;
    const float rinv = rsqrtf(var + 1e-5f);

    const __nv_bfloat162* rh2 = (const __nv_bfloat162*)(xh + (size_t)b * 2048);
    const __nv_bfloat162* rl2 = (const __nv_bfloat162*)(xl + (size_t)b * 2048);
    const float4* g4 = (const float4*)gamma;
    const float4* bt4 = (const float4*)beta;
    float4* o4 = (float4*)(out + (size_t)b * 2048);
    #pragma unroll
    for (int j = 0; j < 2; j++) {
        const int c4 = tid + j * 256;
        float4 g = g4[c4], bt = bt4[c4];
        __nv_bfloat162 rh0 = rh2[2 * c4], rh1 = rh2[2 * c4 + 1];
        __nv_bfloat162 rl0 = rl2[2 * c4], rl1 = rl2[2 * c4 + 1];
        float4 v = vals[j];
        float4 o;
        o.x = (v.x - mu) * rinv * g.x + bt.x +
              __bfloat162float(rh0.x) + __bfloat162float(rl0.x);
        o.y = (v.y - mu) * rinv * g.y + bt.y +
              __bfloat162float(rh0.y) + __bfloat162float(rl0.y);
        o.z = (v.z - mu) * rinv * g.z + bt.z +
              __bfloat162float(rh1.x) + __bfloat162float(rl1.x);
        o.w = (v.w - mu) * rinv * g.w + bt.w +
              __bfloat162float(rh1.y) + __bfloat162float(rl1.y);
        o4[c4] = o;
    }
}

// ---------------------------------------------------------------------------
extern "C" void kernel_launch(void* const* d_in, const int* in_sizes, int n_in,
                              void* d_out, int out_size)
{
    const float* features1 = (const float*)d_in[0];
    const float* features2 = (const float*)d_in[1];
    const float* W1    = (const float*)d_in[2];
    const float* b1    = (const float*)d_in[3];
    const float* W2    = (const float*)d_in[4];
    const float* b2    = (const float*)d_in[5];
    const float* Wqkv  = (const float*)d_in[6];
    const float* Wout  = (const float*)d_in[7];
    const float* bout  = (const float*)d_in[8];
    const float* gamma = (const float*)d_in[9];
    const float* beta  = (const float*)d_in[10];
    float* out = (float*)d_out;

    float *p_qkv, *p_o2;
    __nv_bfloat16 *p_f1h, *p_f2h, *p_xh, *p_xl, *p_ah;
    __nv_bfloat16 *p_w1h, *p_w2h, *p_wqh, *p_woh;
    uint8_t *p_f18h, *p_f18l, *p_f28h, *p_f28l, *p_x8h, *p_x8l, *p_a8h, *p_a8l;
    uint8_t *p_w18h, *p_w18l, *p_w28h, *p_w28l, *p_wq8h, *p_wq8l, *p_wo8h, *p_wo8l;
    cudaGetSymbolAddress((void**)&p_qkv, g_qkv);
    cudaGetSymbolAddress((void**)&p_o2,  g_o2);
    cudaGetSymbolAddress((void**)&p_f1h, g_f1h);
    cudaGetSymbolAddress((void**)&p_f2h, g_f2h);
    cudaGetSymbolAddress((void**)&p_f18h, g_f18h); cudaGetSymbolAddress((void**)&p_f18l, g_f18l);
    cudaGetSymbolAddress((void**)&p_f28h, g_f28h); cudaGetSymbolAddress((void**)&p_f28l, g_f28l);
    cudaGetSymbolAddress((void**)&p_xh,  g_xh);   cudaGetSymbolAddress((void**)&p_xl,  g_xl);
    cudaGetSymbolAddress((void**)&p_x8h, g_x8h);  cudaGetSymbolAddress((void**)&p_x8l, g_x8l);
    cudaGetSymbolAddress((void**)&p_ah,  g_ah);
    cudaGetSymbolAddress((void**)&p_a8h, g_a8h);  cudaGetSymbolAddress((void**)&p_a8l, g_a8l);
    cudaGetSymbolAddress((void**)&p_w1h, g_w1h);
    cudaGetSymbolAddress((void**)&p_w18h, g_w18h); cudaGetSymbolAddress((void**)&p_w18l, g_w18l);
    cudaGetSymbolAddress((void**)&p_w2h, g_w2h);
    cudaGetSymbolAddress((void**)&p_w28h, g_w28h); cudaGetSymbolAddress((void**)&p_w28l, g_w28l);
    cudaGetSymbolAddress((void**)&p_wqh, g_wqh);
    cudaGetSymbolAddress((void**)&p_wq8h, g_wq8h); cudaGetSymbolAddress((void**)&p_wq8l, g_wq8l);
    cudaGetSymbolAddress((void**)&p_woh, g_woh);
    cudaGetSymbolAddress((void**)&p_wo8h, g_wo8h); cudaGetSymbolAddress((void**)&p_wo8l, g_wo8l);

    cudaFuncSetAttribute(gemm_hmma, cudaFuncAttributeMaxDynamicSharedMemorySize,
                         SMEM_BYTES);
    cudaFuncSetAttribute(gemm_proj, cudaFuncAttributeMaxDynamicSharedMemorySize,
                         SMEM_BYTES);

    // ncu (-s 5 -c 1) captures our 4th launch -> keep proj there.
    asplit<<<(size_t)BATCH * IMGDIM / 1024, 256>>>(
        features1, p_f1h, p_f18h, p_f18l, (size_t)BATCH * IMGDIM);               // 1
    asplit<<<(size_t)BATCH * QDIM / 1024, 256>>>(
        features2, p_f2h, p_f28h, p_f28l, (size_t)BATCH * QDIM);                 // 2
    wsplit_v2<<<dim3(HDIM / 32, IMGDIM / 64, 2), 256>>>(
        W1, W2, Wqkv, Wout,
        p_w1h, p_w18h, p_w18l, p_w2h, p_w28h, p_w28l,
        p_wqh, p_wq8h, p_wq8l, p_woh, p_wo8h, p_wo8l, 0);                        // 3
    gemm_proj<<<dim3(HDIM / BN, BATCH / BM, 2), 512, SMEM_BYTES>>>(
        p_f1h, p_f18h, p_f18l, p_w1h, p_w18h, p_w18l, b1,
        p_f2h, p_f28h, p_f28l, p_w2h, p_w28h, p_w28l, b2,
        p_xh, p_xl, p_x8h, p_x8l);                                               // 4
    wsplit_v2<<<dim3(H3 / 32, HDIM / 64, 2), 256>>>(
        W1, W2, Wqkv, Wout,
        p_w1h, p_w18h, p_w18l, p_w2h, p_w28h, p_w28l,
        p_wqh, p_wq8h, p_wq8l, p_woh, p_wo8h, p_wo8l, 2);                        // 5
    gemm_hmma<<<dim3(H3 / BN, B2 / BM), 512, SMEM_BYTES>>>(
        p_xh, p_x8h, p_x8l, p_wqh, p_wq8h, p_wq8l, nullptr, p_qkv, H3, HDIM);    // 6
    attn_kernel<<<BATCH, 128>>>(p_qkv, p_ah, p_a8h, p_a8l);                      // 7
    gemm_hmma<<<dim3(HDIM / BN, B2 / BM), 512, SMEM_BYTES>>>(
        p_ah, p_a8h, p_a8l, p_woh, p_wo8h, p_wo8l, bout, p_o2, HDIM, HDIM);      // 8
    ln_kernel<<<BATCH, 256>>>(p_o2, p_xh, p_xl, gamma, beta, out);               // 9

    (void)in_sizes; (void)n_in; (void)out_size;
}

// round 14
// speedup vs baseline: 1.4095x; 1.4095x over previous
#include <cuda_runtime.h>
#include <cuda_bf16.h>
#include <stdint.h>
#include <math.h>

// ---------------------------------------------------------------------------
// MultiModalAttention (sm_103 base target): HMMA m16n8k16 bf16, 3-term split.
// Round 14: revert to R12 champion (1542us) — fp8 cross-term path (R13) ran
// QMMA at a slow rate and is abandoned. Only change vs R12: the two wsplit
// launches merged into one (z=4, early-return guard).
// ---------------------------------------------------------------------------

#define BATCH   8192
#define IMGDIM  2048
#define QDIM    768
#define HDIM    1024
#define H3      3072
#define B2      16384
#define NHEADS  16
#define HD      64

#define BM 256
#define BN 128
#define BK 32
#define KS_BYTES 80
#define ARR_A (BM * KS_BYTES)             // 20480
#define ARR_B (BN * KS_BYTES)             // 10240
#define OFF_AH 0
#define OFF_AL (ARR_A)
#define OFF_BH (2 * ARR_A)
#define OFF_BL (2 * ARR_A + ARR_B)
#define STAGE_BYTES (2 * ARR_A + 2 * ARR_B)   // 61440
#define NSTAGE 3
#define SMEM_BYTES (NSTAGE * STAGE_BYTES)     // 184320

// ---------------- device scratch ---------------------------------------------
__device__ float g_qkv[(size_t)B2 * H3];
__device__ float g_o2 [(size_t)B2 * HDIM];

__device__ __nv_bfloat16 g_f1h[(size_t)BATCH * IMGDIM], g_f1l[(size_t)BATCH * IMGDIM];
__device__ __nv_bfloat16 g_f2h[(size_t)BATCH * QDIM],  g_f2l[(size_t)BATCH * QDIM];
__device__ __nv_bfloat16 g_xh [(size_t)B2 * HDIM],     g_xl [(size_t)B2 * HDIM];
__device__ __nv_bfloat16 g_ah [(size_t)B2 * HDIM],     g_al [(size_t)B2 * HDIM];
__device__ __nv_bfloat16 g_w1h[(size_t)HDIM * IMGDIM], g_w1l[(size_t)HDIM * IMGDIM];
__device__ __nv_bfloat16 g_w2h[(size_t)HDIM * QDIM],   g_w2l[(size_t)HDIM * QDIM];
__device__ __nv_bfloat16 g_wqh[(size_t)H3 * HDIM],     g_wql[(size_t)H3 * HDIM];
__device__ __nv_bfloat16 g_woh[(size_t)HDIM * HDIM],   g_wol[(size_t)HDIM * HDIM];

// ---------------- helpers ------------------------------------------------------
__device__ __forceinline__ uint32_t smem_u32(const void* p) {
    return (uint32_t)__cvta_generic_to_shared(p);
}
__device__ __forceinline__ void cp16(uint32_t s, const void* g) {
    asm volatile("cp.async.cg.shared.global [%0], [%1], 16;"
                 :: "r"(s), "l"(__cvta_generic_to_global(g)) : "memory");
}
#define LDMX4(r, addr) \
    asm volatile("ldmatrix.sync.aligned.m8n8.x4.shared.b16 {%0,%1,%2,%3}, [%4];" \
        : "=r"((r)[0]), "=r"((r)[1]), "=r"((r)[2]), "=r"((r)[3]) : "r"(addr))
#define MMA16816(c, a, b0, b1) \
    asm volatile("mma.sync.aligned.m16n8k16.row.col.f32.bf16.bf16.f32 " \
        "{%0,%1,%2,%3}, {%4,%5,%6,%7}, {%8,%9}, {%0,%1,%2,%3};" \
        : "+f"((c)[0]), "+f"((c)[1]), "+f"((c)[2]), "+f"((c)[3]) \
        : "r"((a)[0]), "r"((a)[1]), "r"((a)[2]), "r"((a)[3]), "r"(b0), "r"(b1))

// ---------------- stage loader (512 threads, 6 cp.async each) -----------------
__device__ __forceinline__ void load_stage(
    uint32_t st, int tid,
    const __nv_bfloat16* __restrict__ Ah, const __nv_bfloat16* __restrict__ Al,
    const __nv_bfloat16* __restrict__ Bh, const __nv_bfloat16* __restrict__ Bl,
    int bm, int bn, int K, int k0)
{
    const int q  = tid & 3;
    const int rb = tid >> 2;     // 0..127
    #pragma unroll
    for (int t = 0; t < 6; t++) {
        const __nv_bfloat16* g;
        uint32_t sa;
        if (t < 2) {
            const int r = t * 128 + rb;
            g  = Ah + (size_t)(bm + r) * K + k0 + q * 8;
            sa = st + OFF_AH + (uint32_t)r * KS_BYTES + q * 16;
        } else if (t < 4) {
            const int r = (t - 2) * 128 + rb;
            g  = Al + (size_t)(bm + r) * K + k0 + q * 8;
            sa = st + OFF_AL + (uint32_t)r * KS_BYTES + q * 16;
        } else if (t == 4) {
            g  = Bh + (size_t)(bn + rb) * K + k0 + q * 8;
            sa = st + OFF_BH + (uint32_t)rb * KS_BYTES + q * 16;
        } else {
            g  = Bl + (size_t)(bn + rb) * K + k0 + q * 8;
            sa = st + OFF_BL + (uint32_t)rb * KS_BYTES + q * 16;
        }
        cp16(sa, g);
    }
    asm volatile("cp.async.commit_group;" ::: "memory");
}

// ---------------- shared GEMM body (R6/R10 schedule, verbatim) ------------------
__device__ __forceinline__ void gemm_body(
    const __nv_bfloat16* __restrict__ Ah, const __nv_bfloat16* __restrict__ Al,
    const __nv_bfloat16* __restrict__ Bh, const __nv_bfloat16* __restrict__ Bl,
    const float* __restrict__ bias,
    float* __restrict__ outF, __nv_bfloat16* __restrict__ outH,
    __nv_bfloat16* __restrict__ outL,
    int N, int K, int row_mul, int row_off, int bm, int bn, uint32_t sb)
{
    const int tid   = threadIdx.x;
    const int wid   = tid >> 5;
    const int lane  = tid & 31;
    const int warpM = wid >> 2;      // 0..3 -> 64 rows each
    const int warpN = wid & 3;       // 0..3 -> 32 cols each

    float c[4][4][4];                // 64 regs
    #pragma unroll
    for (int i = 0; i < 4; i++)
        #pragma unroll
        for (int j = 0; j < 4; j++)
            #pragma unroll
            for (int k = 0; k < 4; k++) c[i][j][k] = 0.0f;

    const int NT = K / BK;
    load_stage(sb,               tid, Ah, Al, Bh, Bl, bm, bn, K, 0);
    load_stage(sb + STAGE_BYTES, tid, Ah, Al, Bh, Bl, bm, bn, K, BK);

    const int g8 = lane >> 3, lr = lane & 7;
    const int a_row = warpM * 64 + ((g8 & 1) ? 8 : 0) + lr;   // + mt*16
    const int a_kb  = (g8 >> 1) ? 16 : 0;
    const int b_row = warpN * 32 + ((g8 >> 1) ? 8 : 0) + lr;  // + n16*16
    const int b_kb  = (g8 & 1) ? 16 : 0;

    for (int kt = 0; kt < NT; kt++) {
        if (kt + 1 < NT) asm volatile("cp.async.wait_group 1;" ::: "memory");
        else             asm volatile("cp.async.wait_group 0;" ::: "memory");
        __syncthreads();

        const uint32_t st = sb + (uint32_t)(kt % NSTAGE) * STAGE_BYTES;
        #pragma unroll
        for (int kk = 0; kk < 2; kk++) {
            const int kb = kk * 32;
            uint32_t ah[4][4], al[4][4];
            #pragma unroll
            for (int mt = 0; mt < 4; mt++) {
                uint32_t aaddr = st + OFF_AH +
                    (uint32_t)(a_row + mt * 16) * KS_BYTES + a_kb + kb;
                LDMX4(ah[mt], aaddr);
                LDMX4(al[mt], aaddr + ARR_A);
            }
            #pragma unroll
            for (int n16 = 0; n16 < 2; n16++) {
                uint32_t baddr = st + OFF_BH +
                    (uint32_t)(b_row + n16 * 16) * KS_BYTES + b_kb + kb;
                uint32_t bh[4], bl[4];
                LDMX4(bh, baddr);
                LDMX4(bl, baddr + ARR_B);
                #pragma unroll
                for (int mt = 0; mt < 4; mt++)
                    #pragma unroll
                    for (int nn = 0; nn < 2; nn++)
                        MMA16816(c[mt][n16 * 2 + nn], ah[mt], bh[2*nn], bh[2*nn+1]);
                #pragma unroll
                for (int mt = 0; mt < 4; mt++)
                    #pragma unroll
                    for (int nn = 0; nn < 2; nn++)
                        MMA16816(c[mt][n16 * 2 + nn], ah[mt], bl[2*nn], bl[2*nn+1]);
                #pragma unroll
                for (int mt = 0; mt < 4; mt++)
                    #pragma unroll
                    for (int nn = 0; nn < 2; nn++)
                        MMA16816(c[mt][n16 * 2 + nn], al[mt], bh[2*nn], bh[2*nn+1]);
            }
        }
        if (kt + 2 < NT)
            load_stage(sb + (uint32_t)((kt + 2) % NSTAGE) * STAGE_BYTES,
                       tid, Ah, Al, Bh, Bl, bm, bn, K, (kt + 2) * BK);
    }

    // ---- epilogue ----
    const int quad = lane >> 2;
    const int tq   = lane & 3;
    #pragma unroll
    for (int nt = 0; nt < 4; nt++) {
        const int col = bn + warpN * 32 + nt * 8 + tq * 2;
        float bv0 = 0.0f, bv1 = 0.0f;
        if (bias) { bv0 = bias[col]; bv1 = bias[col + 1]; }
        #pragma unroll
        for (int mt = 0; mt < 4; mt++) {
            #pragma unroll
            for (int half = 0; half < 2; half++) {
                const int grow = bm + warpM * 64 + mt * 16 + half * 8 + quad;
                const size_t off = ((size_t)grow * row_mul + row_off) * N + col;
                float v0 = c[mt][nt][2 * half + 0] + bv0;
                float v1 = c[mt][nt][2 * half + 1] + bv1;
                if (outF) *(float2*)(outF + off) = make_float2(v0, v1);
                if (outH) {
                    __nv_bfloat16 h0 = __float2bfloat16(v0);
                    __nv_bfloat16 h1 = __float2bfloat16(v1);
                    __nv_bfloat162 hp; hp.x = h0; hp.y = h1;
                    *(__nv_bfloat162*)(outH + off) = hp;
                    __nv_bfloat162 lp;
                    lp.x = __float2bfloat16(v0 - __bfloat162float(h0));
                    lp.y = __float2bfloat16(v1 - __bfloat162float(h1));
                    *(__nv_bfloat162*)(outL + off) = lp;
                }
            }
        }
    }
}

// ---------------- GEMM kernels -------------------------------------------------
__global__ void __launch_bounds__(512, 1)
gemm_hmma(const __nv_bfloat16* __restrict__ Ah, const __nv_bfloat16* __restrict__ Al,
          const __nv_bfloat16* __restrict__ Bh, const __nv_bfloat16* __restrict__ Bl,
          const float* __restrict__ bias, float* __restrict__ outF,
          int N, int K)
{
    extern __shared__ char smem[];
    gemm_body(Ah, Al, Bh, Bl, bias, outF, nullptr, nullptr,
              N, K, 1, 0, blockIdx.y * BM, blockIdx.x * BN, smem_u32(smem));
}

// merged f1/f2 projection: blockIdx.z = modality
__global__ void __launch_bounds__(512, 1)
gemm_proj(const __nv_bfloat16* __restrict__ f1h, const __nv_bfloat16* __restrict__ f1l,
          const __nv_bfloat16* __restrict__ w1h, const __nv_bfloat16* __restrict__ w1l,
          const float* __restrict__ b1,
          const __nv_bfloat16* __restrict__ f2h, const __nv_bfloat16* __restrict__ f2l,
          const __nv_bfloat16* __restrict__ w2h, const __nv_bfloat16* __restrict__ w2l,
          const float* __restrict__ b2,
          __nv_bfloat16* __restrict__ xh, __nv_bfloat16* __restrict__ xl)
{
    extern __shared__ char smem[];
    if (blockIdx.z == 0)
        gemm_body(f1h, f1l, w1h, w1l, b1, nullptr, xh, xl,
                  HDIM, IMGDIM, 2, 0, blockIdx.y * BM, blockIdx.x * BN,
                  smem_u32(smem));
    else
        gemm_body(f2h, f2l, w2h, w2l, b2, nullptr, xh, xl,
                  HDIM, QDIM, 2, 1, blockIdx.y * BM, blockIdx.x * BN,
                  smem_u32(smem));
}

// ---------------- elementwise split (activations) ----------------------------
__global__ void __launch_bounds__(256)
asplit(const float* __restrict__ x, __nv_bfloat16* __restrict__ h,
       __nv_bfloat16* __restrict__ l, size_t n)
{
    size_t i = ((size_t)blockIdx.x * 256 + threadIdx.x) * 4;
    if (i >= n) return;
    float4 v = *(const float4*)(x + i);
    __nv_bfloat16 h0 = __float2bfloat16(v.x), h1 = __float2bfloat16(v.y);
    __nv_bfloat16 h2 = __float2bfloat16(v.z), h3 = __float2bfloat16(v.w);
    __nv_bfloat162 hp0; hp0.x = h0; hp0.y = h1;
    __nv_bfloat162 hp1; hp1.x = h2; hp1.y = h3;
    *(__nv_bfloat162*)(h + i)     = hp0;
    *(__nv_bfloat162*)(h + i + 2) = hp1;
    __nv_bfloat162 lp0, lp1;
    lp0.x = __float2bfloat16(v.x - __bfloat162float(h0));
    lp0.y = __float2bfloat16(v.y - __bfloat162float(h1));
    lp1.x = __float2bfloat16(v.z - __bfloat162float(h2));
    lp1.y = __float2bfloat16(v.w - __bfloat162float(h3));
    *(__nv_bfloat162*)(l + i)     = lp0;
    *(__nv_bfloat162*)(l + i + 2) = lp1;
}

// ---------------- weight transpose+split, vectorized, all 4 in one launch ------
__global__ void __launch_bounds__(256)
wsplit_v2(const float* __restrict__ W1, const float* __restrict__ W2,
          const float* __restrict__ Wq, const float* __restrict__ Wo,
          __nv_bfloat16* __restrict__ w1h, __nv_bfloat16* __restrict__ w1l,
          __nv_bfloat16* __restrict__ w2h, __nv_bfloat16* __restrict__ w2l,
          __nv_bfloat16* __restrict__ wqh, __nv_bfloat16* __restrict__ wql,
          __nv_bfloat16* __restrict__ woh, __nv_bfloat16* __restrict__ wol)
{
    const float* W; __nv_bfloat16 *th, *tl; int K, N;
    switch (blockIdx.z) {
        case 0: W = W1; th = w1h; tl = w1l; K = IMGDIM; N = HDIM; break;
        case 1: W = W2; th = w2h; tl = w2l; K = QDIM;   N = HDIM; break;
        case 2: W = Wq; th = wqh; tl = wql; K = HDIM;   N = H3;   break;
        default:W = Wo; th = woh; tl = wol; K = HDIM;   N = HDIM; break;
    }
    const int n0 = blockIdx.x * 32, k0 = blockIdx.y * 64;
    if (n0 >= N || k0 >= K) return;

    __shared__ float tile[64][33];
    const int tx = threadIdx.x & 31, ty = threadIdx.x >> 5;   // (32, 8)
    #pragma unroll
    for (int i = ty; i < 64; i += 8)
        tile[i][tx] = W[(size_t)(k0 + i) * N + n0 + tx];
    __syncthreads();
    #pragma unroll
    for (int i = 0; i < 4; i++) {
        const int nn = ty + i * 8;
        const int n = n0 + nn;
        float v0 = tile[2 * tx + 0][nn];
        float v1 = tile[2 * tx + 1][nn];
        __nv_bfloat16 h0 = __float2bfloat16(v0);
        __nv_bfloat16 h1 = __float2bfloat16(v1);
        __nv_bfloat162 hp; hp.x = h0; hp.y = h1;
        __nv_bfloat162 lp;
        lp.x = __float2bfloat16(v0 - __bfloat162float(h0));
        lp.y = __float2bfloat16(v1 - __bfloat162float(h1));
        const size_t off = (size_t)n * K + k0 + 2 * tx;
        *(__nv_bfloat162*)(th + off) = hp;
        *(__nv_bfloat162*)(tl + off) = lp;
    }
}

// ---------------- attention (2x2 per head) + split output --------------------
__global__ void __launch_bounds__(128)
attn_kernel(const float* __restrict__ qkv, __nv_bfloat16* __restrict__ oh,
            __nv_bfloat16* __restrict__ ol)
{
    const int b = blockIdx.x;
    const int warp = threadIdx.x >> 5;
    const int lane = threadIdx.x & 31;
    const float scale = 0.125f;
    const size_t base0 = (size_t)(2 * b) * H3;
    const size_t base1 = base0 + H3;

    #pragma unroll
    for (int h = warp; h < NHEADS; h += 4) {
        const int off = h * HD + lane;
        float q0a = qkv[base0 + off],          q0b = qkv[base0 + off + 32];
        float k0a = qkv[base0 + HDIM + off],   k0b = qkv[base0 + HDIM + off + 32];
        float v0a = qkv[base0 + 2*HDIM + off], v0b = qkv[base0 + 2*HDIM + off + 32];
        float q1a = qkv[base1 + off],          q1b = qkv[base1 + off + 32];
        float k1a = qkv[base1 + HDIM + off],   k1b = qkv[base1 + HDIM + off + 32];
        float v1a = qkv[base1 + 2*HDIM + off], v1b = qkv[base1 + 2*HDIM + off + 32];

        float s00 = q0a * k0a + q0b * k0b;
        float s01 = q0a * k1a + q0b * k1b;
        float s10 = q1a * k0a + q1b * k0b;
        float s11 = q1a * k1a + q1b * k1b;
        #pragma unroll
        for (int d = 16; d; d >>= 1) {
            s00 += __shfl_xor_sync(0xffffffffu, s00, d);
            s01 += __shfl_xor_sync(0xffffffffu, s01, d);
            s10 += __shfl_xor_sync(0xffffffffu, s10, d);
            s11 += __shfl_xor_sync(0xffffffffu, s11, d);
        }
        s00 *= scale; s01 *= scale; s10 *= scale; s11 *= scale;

        float m0 = fmaxf(s00, s01), m1 = fmaxf(s10, s11);
        float e00 = __expf(s00 - m0), e01 = __expf(s01 - m0);
        float e10 = __expf(s10 - m1), e11 = __expf(s11 - m1);
        float inv0 = 1.0f / (e00 + e01), inv1 = 1.0f / (e10 + e11);
        float p00 = e00 * inv0, p01 = e01 * inv0;
        float p10 = e10 * inv1, p11 = e11 * inv1;

        float r0 = p00 * v0a + p01 * v1a;
        float r1 = p00 * v0b + p01 * v1b;
        float r2 = p10 * v0a + p11 * v1a;
        float r3 = p10 * v0b + p11 * v1b;

        size_t o0 = (size_t)(2 * b) * HDIM + h * HD + lane;
        size_t o1 = o0 + HDIM;
        __nv_bfloat16 h0 = __float2bfloat16(r0);
        __nv_bfloat16 h1 = __float2bfloat16(r1);
        __nv_bfloat16 h2 = __float2bfloat16(r2);
        __nv_bfloat16 h3 = __float2bfloat16(r3);
        oh[o0] = h0;      oh[o0 + 32] = h1;
        oh[o1] = h2;      oh[o1 + 32] = h3;
        ol[o0]      = __float2bfloat16(r0 - __bfloat162float(h0));
        ol[o0 + 32] = __float2bfloat16(r1 - __bfloat162float(h1));
        ol[o1]      = __float2bfloat16(r2 - __bfloat162float(h2));
        ol[o1 + 32] = __float2bfloat16(r3 - __bfloat162float(h3));
    }
}

// ---------------- LayerNorm(2048) + residual(hi+lo), vectorized ----------------
__global__ void __launch_bounds__(256)
ln_kernel(const float* __restrict__ o2,
          const __nv_bfloat16* __restrict__ xh, const __nv_bfloat16* __restrict__ xl,
          const float* __restrict__ gamma, const float* __restrict__ beta,
          float* __restrict__ out)
{
    const int b = blockIdx.x;
    const int tid = threadIdx.x;
    const float4* x4 = (const float4*)(o2 + (size_t)b * 2048);

    float4 vals[2];
    float sum = 0.0f, sq = 0.0f;
    #pragma unroll
    for (int j = 0; j < 2; j++) {
        float4 v = x4[tid + j * 256];
        vals[j] = v;
        sum += v.x + v.y + v.z + v.w;
        sq  += v.x * v.x + v.y * v.y + v.z * v.z + v.w * v.w;
    }
    #pragma unroll
    for (int d = 16; d; d >>= 1) {
        sum += __shfl_xor_sync(0xffffffffu, sum, d);
        sq  += __shfl_xor_sync(0xffffffffu, sq, d);
    }
    __shared__ float ssum[8], ssq[8];
    const int warp = tid >> 5, lane = tid & 31;
    if (lane == 0) { ssum[warp] = sum; ssq[warp] = sq; }
    __syncthreads();
    float tsum = 0.0f, tsq = 0.0f;
    #pragma unroll
    for (int w = 0; w < 8; w++) { tsum += ssum[w]; tsq += ssq[w]; }

    const float mu   = tsum * (1.0f / 2048.0f);
    const float var  = tsq * (1.0f / 2048.0f) - mu * mu;
    const float rinv = rsqrtf(var + 1e-5f);

    const __nv_bfloat162* rh2 = (const __nv_bfloat162*)(xh + (size_t)b * 2048);
    const __nv_bfloat162* rl2 = (const __nv_bfloat162*)(xl + (size_t)b * 2048);
    const float4* g4 = (const float4*)gamma;
    const float4* bt4 = (const float4*)beta;
    float4* o4 = (float4*)(out + (size_t)b * 2048);
    #pragma unroll
    for (int j = 0; j < 2; j++) {
        const int c4 = tid + j * 256;
        float4 g = g4[c4], bt = bt4[c4];
        __nv_bfloat162 rh0 = rh2[2 * c4], rh1 = rh2[2 * c4 + 1];
        __nv_bfloat162 rl0 = rl2[2 * c4], rl1 = rl2[2 * c4 + 1];
        float4 v = vals[j];
        float4 o;
        o.x = (v.x - mu) * rinv * g.x + bt.x +
              __bfloat162float(rh0.x) + __bfloat162float(rl0.x);
        o.y = (v.y - mu) * rinv * g.y + bt.y +
              __bfloat162float(rh0.y) + __bfloat162float(rl0.y);
        o.z = (v.z - mu) * rinv * g.z + bt.z +
              __bfloat162float(rh1.x) + __bfloat162float(rl1.x);
        o.w = (v.w - mu) * rinv * g.w + bt.w +
              __bfloat162float(rh1.y) + __bfloat162float(rl1.y);
        o4[c4] = o;
    }
}

// ---------------------------------------------------------------------------
extern "C" void kernel_launch(void* const* d_in, const int* in_sizes, int n_in,
                              void* d_out, int out_size)
{
    const float* features1 = (const float*)d_in[0];
    const float* features2 = (const float*)d_in[1];
    const float* W1    = (const float*)d_in[2];
    const float* b1    = (const float*)d_in[3];
    const float* W2    = (const float*)d_in[4];
    const float* b2    = (const float*)d_in[5];
    const float* Wqkv  = (const float*)d_in[6];
    const float* Wout  = (const float*)d_in[7];
    const float* bout  = (const float*)d_in[8];
    const float* gamma = (const float*)d_in[9];
    const float* beta  = (const float*)d_in[10];
    float* out = (float*)d_out;

    float *p_qkv, *p_o2;
    __nv_bfloat16 *p_f1h, *p_f1l, *p_f2h, *p_f2l, *p_xh, *p_xl, *p_ah, *p_al;
    __nv_bfloat16 *p_w1h, *p_w1l, *p_w2h, *p_w2l, *p_wqh, *p_wql, *p_woh, *p_wol;
    cudaGetSymbolAddress((void**)&p_qkv, g_qkv);
    cudaGetSymbolAddress((void**)&p_o2,  g_o2);
    cudaGetSymbolAddress((void**)&p_f1h, g_f1h); cudaGetSymbolAddress((void**)&p_f1l, g_f1l);
    cudaGetSymbolAddress((void**)&p_f2h, g_f2h); cudaGetSymbolAddress((void**)&p_f2l, g_f2l);
    cudaGetSymbolAddress((void**)&p_xh,  g_xh);  cudaGetSymbolAddress((void**)&p_xl,  g_xl);
    cudaGetSymbolAddress((void**)&p_ah,  g_ah);  cudaGetSymbolAddress((void**)&p_al,  g_al);
    cudaGetSymbolAddress((void**)&p_w1h, g_w1h); cudaGetSymbolAddress((void**)&p_w1l, g_w1l);
    cudaGetSymbolAddress((void**)&p_w2h, g_w2h); cudaGetSymbolAddress((void**)&p_w2l, g_w2l);
    cudaGetSymbolAddress((void**)&p_wqh, g_wqh); cudaGetSymbolAddress((void**)&p_wql, g_wql);
    cudaGetSymbolAddress((void**)&p_woh, g_woh); cudaGetSymbolAddress((void**)&p_wol, g_wol);

    cudaFuncSetAttribute(gemm_hmma, cudaFuncAttributeMaxDynamicSharedMemorySize,
                         SMEM_BYTES);
    cudaFuncSetAttribute(gemm_proj, cudaFuncAttributeMaxDynamicSharedMemorySize,
                         SMEM_BYTES);

    // ncu (-s 5 -c 1) captures our 4th launch -> keep proj there.
    asplit<<<(size_t)BATCH * IMGDIM / 1024, 256>>>(features1, p_f1h, p_f1l,
                                                   (size_t)BATCH * IMGDIM);       // 1
    asplit<<<(size_t)BATCH * QDIM / 1024, 256>>>(features2, p_f2h, p_f2l,
                                                 (size_t)BATCH * QDIM);           // 2
    // all 4 weight transposes in one launch (early-return guards cover the
    // smaller K/N cases); grid sized for the largest (N=H3, K=IMGDIM).
    wsplit_v2<<<dim3(H3 / 32, IMGDIM / 64, 4), 256>>>(
        W1, W2, Wqkv, Wout, p_w1h, p_w1l, p_w2h, p_w2l,
        p_wqh, p_wql, p_woh, p_wol);                                              // 3
    // merged f1/f2 projections -> x hi/lo (profiled launch)
    gemm_proj<<<dim3(HDIM / BN, BATCH / BM, 2), 512, SMEM_BYTES>>>(
        p_f1h, p_f1l, p_w1h, p_w1l, b1,
        p_f2h, p_f2l, p_w2h, p_w2l, b2, p_xh, p_xl);                              // 4
    // G3: x @ Wqkv -> qkv fp32
    gemm_hmma<<<dim3(H3 / BN, B2 / BM), 512, SMEM_BYTES>>>(
        p_xh, p_xl, p_wqh, p_wql, nullptr, p_qkv, H3, HDIM);                      // 5
    attn_kernel<<<BATCH, 128>>>(p_qkv, p_ah, p_al);                               // 6
    // G4: att @ Wout + bout -> o2 fp32
    gemm_hmma<<<dim3(HDIM / BN, B2 / BM), 512, SMEM_BYTES>>>(
        p_ah, p_al, p_woh, p_wol, bout, p_o2, HDIM, HDIM);                        // 7
    ln_kernel<<<BATCH, 256>>>(p_o2, p_xh, p_xl, gamma, beta, out);                // 8

    (void)in_sizes; (void)n_in; (void)out_size;
}

// round 15
// speedup vs baseline: 1.4657x; 1.0398x over previous
#include <cuda_runtime.h>
#include <cuda_bf16.h>
#include <stdint.h>
#include <math.h>

// ---------------------------------------------------------------------------
// MultiModalAttention (sm_103 base target): HMMA m16n8k16 bf16, 3-term split.
// Round 15: champion (R14, 1540us) + split-K=2 on the Wout GEMM (G4) to kill
// its 13.5% wave-quantization tail; the K-half reduction and bias fuse into
// the LayerNorm. Both asplit launches merged. GEMM core untouched.
// ---------------------------------------------------------------------------

#define BATCH   8192
#define IMGDIM  2048
#define QDIM    768
#define HDIM    1024
#define H3      3072
#define B2      16384
#define NHEADS  16
#define HD      64

#define BM 256
#define BN 128
#define BK 32
#define KS_BYTES 80
#define ARR_A (BM * KS_BYTES)             // 20480
#define ARR_B (BN * KS_BYTES)             // 10240
#define OFF_AH 0
#define OFF_AL (ARR_A)
#define OFF_BH (2 * ARR_A)
#define OFF_BL (2 * ARR_A + ARR_B)
#define STAGE_BYTES (2 * ARR_A + 2 * ARR_B)   // 61440
#define NSTAGE 3
#define SMEM_BYTES (NSTAGE * STAGE_BYTES)     // 184320

// ---------------- device scratch ---------------------------------------------
__device__ float g_qkv[(size_t)B2 * H3];
__device__ float g_o2a[(size_t)B2 * HDIM];
__device__ float g_o2b[(size_t)B2 * HDIM];

__device__ __nv_bfloat16 g_f1h[(size_t)BATCH * IMGDIM], g_f1l[(size_t)BATCH * IMGDIM];
__device__ __nv_bfloat16 g_f2h[(size_t)BATCH * QDIM],  g_f2l[(size_t)BATCH * QDIM];
__device__ __nv_bfloat16 g_xh [(size_t)B2 * HDIM],     g_xl [(size_t)B2 * HDIM];
__device__ __nv_bfloat16 g_ah [(size_t)B2 * HDIM],     g_al [(size_t)B2 * HDIM];
__device__ __nv_bfloat16 g_w1h[(size_t)HDIM * IMGDIM], g_w1l[(size_t)HDIM * IMGDIM];
__device__ __nv_bfloat16 g_w2h[(size_t)HDIM * QDIM],   g_w2l[(size_t)HDIM * QDIM];
__device__ __nv_bfloat16 g_wqh[(size_t)H3 * HDIM],     g_wql[(size_t)H3 * HDIM];
__device__ __nv_bfloat16 g_woh[(size_t)HDIM * HDIM],   g_wol[(size_t)HDIM * HDIM];

// ---------------- helpers ------------------------------------------------------
__device__ __forceinline__ uint32_t smem_u32(const void* p) {
    return (uint32_t)__cvta_generic_to_shared(p);
}
__device__ __forceinline__ void cp16(uint32_t s, const void* g) {
    asm volatile("cp.async.cg.shared.global [%0], [%1], 16;"
                 :: "r"(s), "l"(__cvta_generic_to_global(g)) : "memory");
}
#define LDMX4(r, addr) \
    asm volatile("ldmatrix.sync.aligned.m8n8.x4.shared.b16 {%0,%1,%2,%3}, [%4];" \
        : "=r"((r)[0]), "=r"((r)[1]), "=r"((r)[2]), "=r"((r)[3]) : "r"(addr))
#define MMA16816(c, a, b0, b1) \
    asm volatile("mma.sync.aligned.m16n8k16.row.col.f32.bf16.bf16.f32 " \
        "{%0,%1,%2,%3}, {%4,%5,%6,%7}, {%8,%9}, {%0,%1,%2,%3};" \
        : "+f"((c)[0]), "+f"((c)[1]), "+f"((c)[2]), "+f"((c)[3]) \
        : "r"((a)[0]), "r"((a)[1]), "r"((a)[2]), "r"((a)[3]), "r"(b0), "r"(b1))

// ---------------- stage loader (512 threads, 6 cp.async each) -----------------
// ldK = row stride in elements; k0 = start column within the row.
__device__ __forceinline__ void load_stage(
    uint32_t st, int tid,
    const __nv_bfloat16* __restrict__ Ah, const __nv_bfloat16* __restrict__ Al,
    const __nv_bfloat16* __restrict__ Bh, const __nv_bfloat16* __restrict__ Bl,
    int bm, int bn, int ldK, int k0)
{
    const int q  = tid & 3;
    const int rb = tid >> 2;     // 0..127
    #pragma unroll
    for (int t = 0; t < 6; t++) {
        const __nv_bfloat16* g;
        uint32_t sa;
        if (t < 2) {
            const int r = t * 128 + rb;
            g  = Ah + (size_t)(bm + r) * ldK + k0 + q * 8;
            sa = st + OFF_AH + (uint32_t)r * KS_BYTES + q * 16;
        } else if (t < 4) {
            const int r = (t - 2) * 128 + rb;
            g  = Al + (size_t)(bm + r) * ldK + k0 + q * 8;
            sa = st + OFF_AL + (uint32_t)r * KS_BYTES + q * 16;
        } else if (t == 4) {
            g  = Bh + (size_t)(bn + rb) * ldK + k0 + q * 8;
            sa = st + OFF_BH + (uint32_t)rb * KS_BYTES + q * 16;
        } else {
            g  = Bl + (size_t)(bn + rb) * ldK + k0 + q * 8;
            sa = st + OFF_BL + (uint32_t)rb * KS_BYTES + q * 16;
        }
        cp16(sa, g);
    }
    asm volatile("cp.async.commit_group;" ::: "memory");
}

// ---------------- shared GEMM body (R6/R10 schedule, verbatim) ------------------
// ldK = row stride; klen = K extent reduced by this CTA (base ptrs pre-offset).
__device__ __forceinline__ void gemm_body(
    const __nv_bfloat16* __restrict__ Ah, const __nv_bfloat16* __restrict__ Al,
    const __nv_bfloat16* __restrict__ Bh, const __nv_bfloat16* __restrict__ Bl,
    const float* __restrict__ bias,
    float* __restrict__ outF, __nv_bfloat16* __restrict__ outH,
    __nv_bfloat16* __restrict__ outL,
    int N, int ldK, int klen, int row_mul, int row_off, int bm, int bn,
    uint32_t sb)
{
    const int tid   = threadIdx.x;
    const int wid   = tid >> 5;
    const int lane  = tid & 31;
    const int warpM = wid >> 2;      // 0..3 -> 64 rows each
    const int warpN = wid & 3;       // 0..3 -> 32 cols each

    float c[4][4][4];                // 64 regs
    #pragma unroll
    for (int i = 0; i < 4; i++)
        #pragma unroll
        for (int j = 0; j < 4; j++)
            #pragma unroll
            for (int k = 0; k < 4; k++) c[i][j][k] = 0.0f;

    const int NT = klen / BK;
    load_stage(sb,               tid, Ah, Al, Bh, Bl, bm, bn, ldK, 0);
    load_stage(sb + STAGE_BYTES, tid, Ah, Al, Bh, Bl, bm, bn, ldK, BK);

    const int g8 = lane >> 3, lr = lane & 7;
    const int a_row = warpM * 64 + ((g8 & 1) ? 8 : 0) + lr;   // + mt*16
    const int a_kb  = (g8 >> 1) ? 16 : 0;
    const int b_row = warpN * 32 + ((g8 >> 1) ? 8 : 0) + lr;  // + n16*16
    const int b_kb  = (g8 & 1) ? 16 : 0;

    for (int kt = 0; kt < NT; kt++) {
        if (kt + 1 < NT) asm volatile("cp.async.wait_group 1;" ::: "memory");
        else             asm volatile("cp.async.wait_group 0;" ::: "memory");
        __syncthreads();

        const uint32_t st = sb + (uint32_t)(kt % NSTAGE) * STAGE_BYTES;
        #pragma unroll
        for (int kk = 0; kk < 2; kk++) {
            const int kb = kk * 32;
            uint32_t ah[4][4], al[4][4];
            #pragma unroll
            for (int mt = 0; mt < 4; mt++) {
                uint32_t aaddr = st + OFF_AH +
                    (uint32_t)(a_row + mt * 16) * KS_BYTES + a_kb + kb;
                LDMX4(ah[mt], aaddr);
                LDMX4(al[mt], aaddr + ARR_A);
            }
            #pragma unroll
            for (int n16 = 0; n16 < 2; n16++) {
                uint32_t baddr = st + OFF_BH +
                    (uint32_t)(b_row + n16 * 16) * KS_BYTES + b_kb + kb;
                uint32_t bh[4], bl[4];
                LDMX4(bh, baddr);
                LDMX4(bl, baddr + ARR_B);
                #pragma unroll
                for (int mt = 0; mt < 4; mt++)
                    #pragma unroll
                    for (int nn = 0; nn < 2; nn++)
                        MMA16816(c[mt][n16 * 2 + nn], ah[mt], bh[2*nn], bh[2*nn+1]);
                #pragma unroll
                for (int mt = 0; mt < 4; mt++)
                    #pragma unroll
                    for (int nn = 0; nn < 2; nn++)
                        MMA16816(c[mt][n16 * 2 + nn], ah[mt], bl[2*nn], bl[2*nn+1]);
                #pragma unroll
                for (int mt = 0; mt < 4; mt++)
                    #pragma unroll
                    for (int nn = 0; nn < 2; nn++)
                        MMA16816(c[mt][n16 * 2 + nn], al[mt], bh[2*nn], bh[2*nn+1]);
            }
        }
        if (kt + 2 < NT)
            load_stage(sb + (uint32_t)((kt + 2) % NSTAGE) * STAGE_BYTES,
                       tid, Ah, Al, Bh, Bl, bm, bn, ldK, (kt + 2) * BK);
    }

    // ---- epilogue ----
    const int quad = lane >> 2;
    const int tq   = lane & 3;
    #pragma unroll
    for (int nt = 0; nt < 4; nt++) {
        const int col = bn + warpN * 32 + nt * 8 + tq * 2;
        float bv0 = 0.0f, bv1 = 0.0f;
        if (bias) { bv0 = bias[col]; bv1 = bias[col + 1]; }
        #pragma unroll
        for (int mt = 0; mt < 4; mt++) {
            #pragma unroll
            for (int half = 0; half < 2; half++) {
                const int grow = bm + warpM * 64 + mt * 16 + half * 8 + quad;
                const size_t off = ((size_t)grow * row_mul + row_off) * N + col;
                float v0 = c[mt][nt][2 * half + 0] + bv0;
                float v1 = c[mt][nt][2 * half + 1] + bv1;
                if (outF) *(float2*)(outF + off) = make_float2(v0, v1);
                if (outH) {
                    __nv_bfloat16 h0 = __float2bfloat16(v0);
                    __nv_bfloat16 h1 = __float2bfloat16(v1);
                    __nv_bfloat162 hp; hp.x = h0; hp.y = h1;
                    *(__nv_bfloat162*)(outH + off) = hp;
                    __nv_bfloat162 lp;
                    lp.x = __float2bfloat16(v0 - __bfloat162float(h0));
                    lp.y = __float2bfloat16(v1 - __bfloat162float(h1));
                    *(__nv_bfloat162*)(outL + off) = lp;
                }
            }
        }
    }
}

// ---------------- GEMM kernels -------------------------------------------------
// gridDim.z = 1: full-K into outF0. gridDim.z = 2: split-K halves into
// outF0/outF1 (reduction happens downstream in ln_kernel).
__global__ void __launch_bounds__(512, 1)
gemm_hmma(const __nv_bfloat16* __restrict__ Ah, const __nv_bfloat16* __restrict__ Al,
          const __nv_bfloat16* __restrict__ Bh, const __nv_bfloat16* __restrict__ Bl,
          float* __restrict__ outF0, float* __restrict__ outF1,
          int N, int ldK)
{
    extern __shared__ char smem[];
    const int klen = ldK / gridDim.z;
    const int k0 = blockIdx.z * klen;
    float* outF = blockIdx.z ? outF1 : outF0;
    gemm_body(Ah + k0, Al + k0, Bh + k0, Bl + k0, nullptr, outF,
              nullptr, nullptr,
              N, ldK, klen, 1, 0, blockIdx.y * BM, blockIdx.x * BN,
              smem_u32(smem));
}

// merged f1/f2 projection: blockIdx.z = modality
__global__ void __launch_bounds__(512, 1)
gemm_proj(const __nv_bfloat16* __restrict__ f1h, const __nv_bfloat16* __restrict__ f1l,
          const __nv_bfloat16* __restrict__ w1h, const __nv_bfloat16* __restrict__ w1l,
          const float* __restrict__ b1,
          const __nv_bfloat16* __restrict__ f2h, const __nv_bfloat16* __restrict__ f2l,
          const __nv_bfloat16* __restrict__ w2h, const __nv_bfloat16* __restrict__ w2l,
          const float* __restrict__ b2,
          __nv_bfloat16* __restrict__ xh, __nv_bfloat16* __restrict__ xl)
{
    extern __shared__ char smem[];
    if (blockIdx.z == 0)
        gemm_body(f1h, f1l, w1h, w1l, b1, nullptr, xh, xl,
                  HDIM, IMGDIM, IMGDIM, 2, 0, blockIdx.y * BM, blockIdx.x * BN,
                  smem_u32(smem));
    else
        gemm_body(f2h, f2l, w2h, w2l, b2, nullptr, xh, xl,
                  HDIM, QDIM, QDIM, 2, 1, blockIdx.y * BM, blockIdx.x * BN,
                  smem_u32(smem));
}

// ---------------- elementwise split (both features, one launch) ----------------
__global__ void __launch_bounds__(256)
asplit_all(const float* __restrict__ x1, __nv_bfloat16* __restrict__ h1,
           __nv_bfloat16* __restrict__ l1,
           const float* __restrict__ x2, __nv_bfloat16* __restrict__ h2,
           __nv_bfloat16* __restrict__ l2)
{
    const float* x; __nv_bfloat16 *h, *l; size_t n;
    if (blockIdx.z == 0) { x = x1; h = h1; l = l1; n = (size_t)BATCH * IMGDIM; }
    else                 { x = x2; h = h2; l = l2; n = (size_t)BATCH * QDIM; }
    size_t i = ((size_t)blockIdx.x * 256 + threadIdx.x) * 4;
    if (i >= n) return;
    float4 v = *(const float4*)(x + i);
    __nv_bfloat16 h0 = __float2bfloat16(v.x), hb1 = __float2bfloat16(v.y);
    __nv_bfloat16 h2b = __float2bfloat16(v.z), h3 = __float2bfloat16(v.w);
    __nv_bfloat162 hp0; hp0.x = h0;  hp0.y = hb1;
    __nv_bfloat162 hp1; hp1.x = h2b; hp1.y = h3;
    *(__nv_bfloat162*)(h + i)     = hp0;
    *(__nv_bfloat162*)(h + i + 2) = hp1;
    __nv_bfloat162 lp0, lp1;
    lp0.x = __float2bfloat16(v.x - __bfloat162float(h0));
    lp0.y = __float2bfloat16(v.y - __bfloat162float(hb1));
    lp1.x = __float2bfloat16(v.z - __bfloat162float(h2b));
    lp1.y = __float2bfloat16(v.w - __bfloat162float(h3));
    *(__nv_bfloat162*)(l + i)     = lp0;
    *(__nv_bfloat162*)(l + i + 2) = lp1;
}

// ---------------- weight transpose+split, vectorized, all 4 in one launch ------
__global__ void __launch_bounds__(256)
wsplit_v2(const float* __restrict__ W1, const float* __restrict__ W2,
          const float* __restrict__ Wq, const float* __restrict__ Wo,
          __nv_bfloat16* __restrict__ w1h, __nv_bfloat16* __restrict__ w1l,
          __nv_bfloat16* __restrict__ w2h, __nv_bfloat16* __restrict__ w2l,
          __nv_bfloat16* __restrict__ wqh, __nv_bfloat16* __restrict__ wql,
          __nv_bfloat16* __restrict__ woh, __nv_bfloat16* __restrict__ wol)
{
    const float* W; __nv_bfloat16 *th, *tl; int K, N;
    switch (blockIdx.z) {
        case 0: W = W1; th = w1h; tl = w1l; K = IMGDIM; N = HDIM; break;
        case 1: W = W2; th = w2h; tl = w2l; K = QDIM;   N = HDIM; break;
        case 2: W = Wq; th = wqh; tl = wql; K = HDIM;   N = H3;   break;
        default:W = Wo; th = woh; tl = wol; K = HDIM;   N = HDIM; break;
    }
    const int n0 = blockIdx.x * 32, k0 = blockIdx.y * 64;
    if (n0 >= N || k0 >= K) return;

    __shared__ float tile[64][33];
    const int tx = threadIdx.x & 31, ty = threadIdx.x >> 5;   // (32, 8)
    #pragma unroll
    for (int i = ty; i < 64; i += 8)
        tile[i][tx] = W[(size_t)(k0 + i) * N + n0 + tx];
    __syncthreads();
    #pragma unroll
    for (int i = 0; i < 4; i++) {
        const int nn = ty + i * 8;
        const int n = n0 + nn;
        float v0 = tile[2 * tx + 0][nn];
        float v1 = tile[2 * tx + 1][nn];
        __nv_bfloat16 h0 = __float2bfloat16(v0);
        __nv_bfloat16 h1 = __float2bfloat16(v1);
        __nv_bfloat162 hp; hp.x = h0; hp.y = h1;
        __nv_bfloat162 lp;
        lp.x = __float2bfloat16(v0 - __bfloat162float(h0));
        lp.y = __float2bfloat16(v1 - __bfloat162float(h1));
        const size_t off = (size_t)n * K + k0 + 2 * tx;
        *(__nv_bfloat162*)(th + off) = hp;
        *(__nv_bfloat162*)(tl + off) = lp;
    }
}

// ---------------- attention (2x2 per head) + split output --------------------
__global__ void __launch_bounds__(128)
attn_kernel(const float* __restrict__ qkv, __nv_bfloat16* __restrict__ oh,
            __nv_bfloat16* __restrict__ ol)
{
    const int b = blockIdx.x;
    const int warp = threadIdx.x >> 5;
    const int lane = threadIdx.x & 31;
    const float scale = 0.125f;
    const size_t base0 = (size_t)(2 * b) * H3;
    const size_t base1 = base0 + H3;

    #pragma unroll
    for (int h = warp; h < NHEADS; h += 4) {
        const int off = h * HD + lane;
        float q0a = qkv[base0 + off],          q0b = qkv[base0 + off + 32];
        float k0a = qkv[base0 + HDIM + off],   k0b = qkv[base0 + HDIM + off + 32];
        float v0a = qkv[base0 + 2*HDIM + off], v0b = qkv[base0 + 2*HDIM + off + 32];
        float q1a = qkv[base1 + off],          q1b = qkv[base1 + off + 32];
        float k1a = qkv[base1 + HDIM + off],   k1b = qkv[base1 + HDIM + off + 32];
        float v1a = qkv[base1 + 2*HDIM + off], v1b = qkv[base1 + 2*HDIM + off + 32];

        float s00 = q0a * k0a + q0b * k0b;
        float s01 = q0a * k1a + q0b * k1b;
        float s10 = q1a * k0a + q1b * k0b;
        float s11 = q1a * k1a + q1b * k1b;
        #pragma unroll
        for (int d = 16; d; d >>= 1) {
            s00 += __shfl_xor_sync(0xffffffffu, s00, d);
            s01 += __shfl_xor_sync(0xffffffffu, s01, d);
            s10 += __shfl_xor_sync(0xffffffffu, s10, d);
            s11 += __shfl_xor_sync(0xffffffffu, s11, d);
        }
        s00 *= scale; s01 *= scale; s10 *= scale; s11 *= scale;

        float m0 = fmaxf(s00, s01), m1 = fmaxf(s10, s11);
        float e00 = __expf(s00 - m0), e01 = __expf(s01 - m0);
        float e10 = __expf(s10 - m1), e11 = __expf(s11 - m1);
        float inv0 = 1.0f / (e00 + e01), inv1 = 1.0f / (e10 + e11);
        float p00 = e00 * inv0, p01 = e01 * inv0;
        float p10 = e10 * inv1, p11 = e11 * inv1;

        float r0 = p00 * v0a + p01 * v1a;
        float r1 = p00 * v0b + p01 * v1b;
        float r2 = p10 * v0a + p11 * v1a;
        float r3 = p10 * v0b + p11 * v1b;

        size_t o0 = (size_t)(2 * b) * HDIM + h * HD + lane;
        size_t o1 = o0 + HDIM;
        __nv_bfloat16 h0 = __float2bfloat16(r0);
        __nv_bfloat16 h1 = __float2bfloat16(r1);
        __nv_bfloat16 h2 = __float2bfloat16(r2);
        __nv_bfloat16 h3 = __float2bfloat16(r3);
        oh[o0] = h0;      oh[o0 + 32] = h1;
        oh[o1] = h2;      oh[o1 + 32] = h3;
        ol[o0]      = __float2bfloat16(r0 - __bfloat162float(h0));
        ol[o0 + 32] = __float2bfloat16(r1 - __bfloat162float(h1));
        ol[o1]      = __float2bfloat16(r2 - __bfloat162float(h2));
        ol[o1 + 32] = __float2bfloat16(r3 - __bfloat162float(h3));
    }
}

// ---------------- LayerNorm(2048): sums split-K halves + bias + residual -------
__global__ void __launch_bounds__(256)
ln_kernel(const float* __restrict__ o2a, const float* __restrict__ o2b,
          const float* __restrict__ bout,
          const __nv_bfloat16* __restrict__ xh, const __nv_bfloat16* __restrict__ xl,
          const float* __restrict__ gamma, const float* __restrict__ beta,
          float* __restrict__ out)
{
    const int b = blockIdx.x;
    const int tid = threadIdx.x;
    const float4* xa4 = (const float4*)(o2a + (size_t)b * 2048);
    const float4* xb4 = (const float4*)(o2b + (size_t)b * 2048);
    const float4* bo4 = (const float4*)bout;     // 256 float4 per token row
    const float4 bv = bo4[tid];                  // same cols for both tokens

    float4 vals[2];
    float sum = 0.0f, sq = 0.0f;
    #pragma unroll
    for (int j = 0; j < 2; j++) {
        const int c4 = tid + j * 256;
        float4 a = xa4[c4], bb = xb4[c4];
        float4 v;
        v.x = a.x + bb.x + bv.x;
        v.y = a.y + bb.y + bv.y;
        v.z = a.z + bb.z + bv.z;
        v.w = a.w + bb.w + bv.w;
        vals[j] = v;
        sum += v.x + v.y + v.z + v.w;
        sq  += v.x * v.x + v.y * v.y + v.z * v.z + v.w * v.w;
    }
    #pragma unroll
    for (int d = 16; d; d >>= 1) {
        sum += __shfl_xor_sync(0xffffffffu, sum, d);
        sq  += __shfl_xor_sync(0xffffffffu, sq, d);
    }
    __shared__ float ssum[8], ssq[8];
    const int warp = tid >> 5, lane = tid & 31;
    if (lane == 0) { ssum[warp] = sum; ssq[warp] = sq; }
    __syncthreads();
    float tsum = 0.0f, tsq = 0.0f;
    #pragma unroll
    for (int w = 0; w < 8; w++) { tsum += ssum[w]; tsq += ssq[w]; }

    const float mu   = tsum * (1.0f / 2048.0f);
    const float var  = tsq * (1.0f / 2048.0f) - mu * mu;
    const float rinv = rsqrtf(var + 1e-5f);

    const __nv_bfloat162* rh2 = (const __nv_bfloat162*)(xh + (size_t)b * 2048);
    const __nv_bfloat162* rl2 = (const __nv_bfloat162*)(xl + (size_t)b * 2048);
    const float4* g4 = (const float4*)gamma;
    const float4* bt4 = (const float4*)beta;
    float4* o4 = (float4*)(out + (size_t)b * 2048);
    #pragma unroll
    for (int j = 0; j < 2; j++) {
        const int c4 = tid + j * 256;
        float4 g = g4[c4], bt = bt4[c4];
        __nv_bfloat162 rh0 = rh2[2 * c4], rh1 = rh2[2 * c4 + 1];
        __nv_bfloat162 rl0 = rl2[2 * c4], rl1 = rl2[2 * c4 + 1];
        float4 v = vals[j];
        float4 o;
        o.x = (v.x - mu) * rinv * g.x + bt.x +
              __bfloat162float(rh0.x) + __bfloat162float(rl0.x);
        o.y = (v.y - mu) * rinv * g.y + bt.y +
              __bfloat162float(rh0.y) + __bfloat162float(rl0.y);
        o.z = (v.z - mu) * rinv * g.z + bt.z +
              __bfloat162float(rh1.x) + __bfloat162float(rl1.x);
        o.w = (v.w - mu) * rinv * g.w + bt.w +
              __bfloat162float(rh1.y) + __bfloat162float(rl1.y);
        o4[c4] = o;
    }
}

// ---------------------------------------------------------------------------
extern "C" void kernel_launch(void* const* d_in, const int* in_sizes, int n_in,
                              void* d_out, int out_size)
{
    const float* features1 = (const float*)d_in[0];
    const float* features2 = (const float*)d_in[1];
    const float* W1    = (const float*)d_in[2];
    const float* b1    = (const float*)d_in[3];
    const float* W2    = (const float*)d_in[4];
    const float* b2    = (const float*)d_in[5];
    const float* Wqkv  = (const float*)d_in[6];
    const float* Wout  = (const float*)d_in[7];
    const float* bout  = (const float*)d_in[8];
    const float* gamma = (const float*)d_in[9];
    const float* beta  = (const float*)d_in[10];
    float* out = (float*)d_out;

    float *p_qkv, *p_o2a, *p_o2b;
    __nv_bfloat16 *p_f1h, *p_f1l, *p_f2h, *p_f2l, *p_xh, *p_xl, *p_ah, *p_al;
    __nv_bfloat16 *p_w1h, *p_w1l, *p_w2h, *p_w2l, *p_wqh, *p_wql, *p_woh, *p_wol;
    cudaGetSymbolAddress((void**)&p_qkv, g_qkv);
    cudaGetSymbolAddress((void**)&p_o2a, g_o2a);
    cudaGetSymbolAddress((void**)&p_o2b, g_o2b);
    cudaGetSymbolAddress((void**)&p_f1h, g_f1h); cudaGetSymbolAddress((void**)&p_f1l, g_f1l);
    cudaGetSymbolAddress((void**)&p_f2h, g_f2h); cudaGetSymbolAddress((void**)&p_f2l, g_f2l);
    cudaGetSymbolAddress((void**)&p_xh,  g_xh);  cudaGetSymbolAddress((void**)&p_xl,  g_xl);
    cudaGetSymbolAddress((void**)&p_ah,  g_ah);  cudaGetSymbolAddress((void**)&p_al,  g_al);
    cudaGetSymbolAddress((void**)&p_w1h, g_w1h); cudaGetSymbolAddress((void**)&p_w1l, g_w1l);
    cudaGetSymbolAddress((void**)&p_w2h, g_w2h); cudaGetSymbolAddress((void**)&p_w2l, g_w2l);
    cudaGetSymbolAddress((void**)&p_wqh, g_wqh); cudaGetSymbolAddress((void**)&p_wql, g_wql);
    cudaGetSymbolAddress((void**)&p_woh, g_woh); cudaGetSymbolAddress((void**)&p_wol, g_wol);

    cudaFuncSetAttribute(gemm_hmma, cudaFuncAttributeMaxDynamicSharedMemorySize,
                         SMEM_BYTES);
    cudaFuncSetAttribute(gemm_proj, cudaFuncAttributeMaxDynamicSharedMemorySize,
                         SMEM_BYTES);

    // launch order: ncu (-s 5 -c 1) lands on our 4th launch -> G3 (qkv GEMM).
    asplit_all<<<dim3((BATCH * IMGDIM + 1023) / 1024, 1, 2), 256>>>(
        features1, p_f1h, p_f1l, features2, p_f2h, p_f2l);                        // 1
    wsplit_v2<<<dim3(H3 / 32, IMGDIM / 64, 4), 256>>>(
        W1, W2, Wqkv, Wout, p_w1h, p_w1l, p_w2h, p_w2l,
        p_wqh, p_wql, p_woh, p_wol);                                              // 2
    gemm_proj<<<dim3(HDIM / BN, BATCH / BM, 2), 512, SMEM_BYTES>>>(
        p_f1h, p_f1l, p_w1h, p_w1l, b1,
        p_f2h, p_f2l, p_w2h, p_w2l, b2, p_xh, p_xl);                              // 3
    // G3: x @ Wqkv -> qkv fp32 (profiled launch)
    gemm_hmma<<<dim3(H3 / BN, B2 / BM, 1), 512, SMEM_BYTES>>>(
        p_xh, p_xl, p_wqh, p_wql, p_qkv, nullptr, H3, HDIM);                      // 4
    attn_kernel<<<BATCH, 128>>>(p_qkv, p_ah, p_al);                               // 5
    // G4: att @ Wout, split-K=2 -> o2a + o2b (bias folded into LN)
    gemm_hmma<<<dim3(HDIM / BN, B2 / BM, 2), 512, SMEM_BYTES>>>(
        p_ah, p_al, p_woh, p_wol, p_o2a, p_o2b, HDIM, HDIM);                      // 6
    ln_kernel<<<BATCH, 256>>>(p_o2a, p_o2b, bout, p_xh, p_xl, gamma, beta, out);  // 7

    (void)in_sizes; (void)n_in; (void)out_size;
}

// round 16
// speedup vs baseline: 1.5975x; 1.0899x over previous
#include <cuda_runtime.h>
#include <cuda_bf16.h>
#include <stdint.h>
#include <math.h>

// ---------------------------------------------------------------------------
// MultiModalAttention (sm_103 base target).
// Round 16: G3 (qkv) and G4 (Wout, split-K=2) switch to SINGLE-term tf32
// m16n8k8 MMA (tensor unit shown MAC-limited by R12/R13 profiles -> 3x less
// MAC work). Operands RNE-rounded to tf32 at producers. proj keeps 3-term
// bf16 (protects the residual path); LN residual stays bf16 hi+lo exact.
// ---------------------------------------------------------------------------

#define BATCH   8192
#define IMGDIM  2048
#define QDIM    768
#define HDIM    1024
#define H3      3072
#define B2      16384
#define NHEADS  16
#define HD      64

// ---- bf16 3-term GEMM tiling (proj) ----
#define BM 256
#define BN 128
#define BK 32
#define KS_BYTES 80
#define ARR_A (BM * KS_BYTES)
#define ARR_B (BN * KS_BYTES)
#define OFF_AH 0
#define OFF_AL (ARR_A)
#define OFF_BH (2 * ARR_A)
#define OFF_BL (2 * ARR_A + ARR_B)
#define STAGE_BYTES (2 * ARR_A + 2 * ARR_B)   // 61440
#define NSTAGE 3
#define SMEM_BYTES (NSTAGE * STAGE_BYTES)     // 184320

// ---- tf32 single-term GEMM tiling (G3/G4) ----
#define KT_BYTES 144                          // 32 f32 = 128B + 16 pad
#define T_ARR_A (BM * KT_BYTES)               // 36864
#define T_ARR_B (BN * KT_BYTES)               // 18432
#define T_OFF_A 0
#define T_OFF_B (T_ARR_A)
#define T_STAGE (T_ARR_A + T_ARR_B)           // 55296
#define T_SMEM  (NSTAGE * T_STAGE)            // 165888

// ---------------- device scratch ---------------------------------------------
__device__ float g_qkv[(size_t)B2 * H3];
__device__ float g_o2a[(size_t)B2 * HDIM];
__device__ float g_o2b[(size_t)B2 * HDIM];
__device__ float g_xt [(size_t)B2 * HDIM];    // tf32-rounded x (G3 A operand)
__device__ float g_att[(size_t)B2 * HDIM];    // tf32-rounded attention out
__device__ float g_wqt[(size_t)H3 * HDIM];    // tf32-rounded Wqkv^T
__device__ float g_wot[(size_t)HDIM * HDIM];  // tf32-rounded Wout^T

__device__ __nv_bfloat16 g_f1h[(size_t)BATCH * IMGDIM], g_f1l[(size_t)BATCH * IMGDIM];
__device__ __nv_bfloat16 g_f2h[(size_t)BATCH * QDIM],  g_f2l[(size_t)BATCH * QDIM];
__device__ __nv_bfloat16 g_xh [(size_t)B2 * HDIM],     g_xl [(size_t)B2 * HDIM];
__device__ __nv_bfloat16 g_w1h[(size_t)HDIM * IMGDIM], g_w1l[(size_t)HDIM * IMGDIM];
__device__ __nv_bfloat16 g_w2h[(size_t)HDIM * QDIM],   g_w2l[(size_t)HDIM * QDIM];

// ---------------- helpers ------------------------------------------------------
__device__ __forceinline__ uint32_t smem_u32(const void* p) {
    return (uint32_t)__cvta_generic_to_shared(p);
}
__device__ __forceinline__ void cp16(uint32_t s, const void* g) {
    asm volatile("cp.async.cg.shared.global [%0], [%1], 16;"
                 :: "r"(s), "l"(__cvta_generic_to_global(g)) : "memory");
}
// round-to-nearest-even onto the tf32 (2^13) boundary; unbiased.
__device__ __forceinline__ uint32_t cvt_tf32(float f) {
    uint32_t x = __float_as_uint(f);
    return (x + 0xFFFu + ((x >> 13) & 1u)) & ~0x1FFFu;
}
#define LDMX4(r, addr) \
    asm volatile("ldmatrix.sync.aligned.m8n8.x4.shared.b16 {%0,%1,%2,%3}, [%4];" \
        : "=r"((r)[0]), "=r"((r)[1]), "=r"((r)[2]), "=r"((r)[3]) : "r"(addr))
#define MMA16816(c, a, b0, b1) \
    asm volatile("mma.sync.aligned.m16n8k16.row.col.f32.bf16.bf16.f32 " \
        "{%0,%1,%2,%3}, {%4,%5,%6,%7}, {%8,%9}, {%0,%1,%2,%3};" \
        : "+f"((c)[0]), "+f"((c)[1]), "+f"((c)[2]), "+f"((c)[3]) \
        : "r"((a)[0]), "r"((a)[1]), "r"((a)[2]), "r"((a)[3]), "r"(b0), "r"(b1))
#define MMATF32(c, a, b0, b1) \
    asm volatile("mma.sync.aligned.m16n8k8.row.col.f32.tf32.tf32.f32 " \
        "{%0,%1,%2,%3}, {%4,%5,%6,%7}, {%8,%9}, {%0,%1,%2,%3};" \
        : "+f"((c)[0]), "+f"((c)[1]), "+f"((c)[2]), "+f"((c)[3]) \
        : "r"((a)[0]), "r"((a)[1]), "r"((a)[2]), "r"((a)[3]), "r"(b0), "r"(b1))
#define LDS32(r, addr) \
    asm volatile("ld.shared.b32 %0, [%1];" : "=r"(r) : "r"(addr))

// ================= bf16 3-term path (proj) — R6/R10 core verbatim ==============
__device__ __forceinline__ void load_stage(
    uint32_t st, int tid,
    const __nv_bfloat16* __restrict__ Ah, const __nv_bfloat16* __restrict__ Al,
    const __nv_bfloat16* __restrict__ Bh, const __nv_bfloat16* __restrict__ Bl,
    int bm, int bn, int ldK, int k0)
{
    const int q  = tid & 3;
    const int rb = tid >> 2;
    #pragma unroll
    for (int t = 0; t < 6; t++) {
        const __nv_bfloat16* g;
        uint32_t sa;
        if (t < 2) {
            const int r = t * 128 + rb;
            g  = Ah + (size_t)(bm + r) * ldK + k0 + q * 8;
            sa = st + OFF_AH + (uint32_t)r * KS_BYTES + q * 16;
        } else if (t < 4) {
            const int r = (t - 2) * 128 + rb;
            g  = Al + (size_t)(bm + r) * ldK + k0 + q * 8;
            sa = st + OFF_AL + (uint32_t)r * KS_BYTES + q * 16;
        } else if (t == 4) {
            g  = Bh + (size_t)(bn + rb) * ldK + k0 + q * 8;
            sa = st + OFF_BH + (uint32_t)rb * KS_BYTES + q * 16;
        } else {
            g  = Bl + (size_t)(bn + rb) * ldK + k0 + q * 8;
            sa = st + OFF_BL + (uint32_t)rb * KS_BYTES + q * 16;
        }
        cp16(sa, g);
    }
    asm volatile("cp.async.commit_group;" ::: "memory");
}

__device__ __forceinline__ void gemm_body(
    const __nv_bfloat16* __restrict__ Ah, const __nv_bfloat16* __restrict__ Al,
    const __nv_bfloat16* __restrict__ Bh, const __nv_bfloat16* __restrict__ Bl,
    const float* __restrict__ bias,
    __nv_bfloat16* __restrict__ outH, __nv_bfloat16* __restrict__ outL,
    float* __restrict__ outT,
    int N, int ldK, int row_mul, int row_off, int bm, int bn, uint32_t sb)
{
    const int tid   = threadIdx.x;
    const int wid   = tid >> 5;
    const int lane  = tid & 31;
    const int warpM = wid >> 2;
    const int warpN = wid & 3;

    float c[4][4][4];
    #pragma unroll
    for (int i = 0; i < 4; i++)
        #pragma unroll
        for (int j = 0; j < 4; j++)
            #pragma unroll
            for (int k = 0; k < 4; k++) c[i][j][k] = 0.0f;

    const int NT = ldK / BK;
    load_stage(sb,               tid, Ah, Al, Bh, Bl, bm, bn, ldK, 0);
    load_stage(sb + STAGE_BYTES, tid, Ah, Al, Bh, Bl, bm, bn, ldK, BK);

    const int g8 = lane >> 3, lr = lane & 7;
    const int a_row = warpM * 64 + ((g8 & 1) ? 8 : 0) + lr;
    const int a_kb  = (g8 >> 1) ? 16 : 0;
    const int b_row = warpN * 32 + ((g8 >> 1) ? 8 : 0) + lr;
    const int b_kb  = (g8 & 1) ? 16 : 0;

    for (int kt = 0; kt < NT; kt++) {
        if (kt + 1 < NT) asm volatile("cp.async.wait_group 1;" ::: "memory");
        else             asm volatile("cp.async.wait_group 0;" ::: "memory");
        __syncthreads();

        const uint32_t st = sb + (uint32_t)(kt % NSTAGE) * STAGE_BYTES;
        #pragma unroll
        for (int kk = 0; kk < 2; kk++) {
            const int kb = kk * 32;
            uint32_t ah[4][4], al[4][4];
            #pragma unroll
            for (int mt = 0; mt < 4; mt++) {
                uint32_t aaddr = st + OFF_AH +
                    (uint32_t)(a_row + mt * 16) * KS_BYTES + a_kb + kb;
                LDMX4(ah[mt], aaddr);
                LDMX4(al[mt], aaddr + ARR_A);
            }
            #pragma unroll
            for (int n16 = 0; n16 < 2; n16++) {
                uint32_t baddr = st + OFF_BH +
                    (uint32_t)(b_row + n16 * 16) * KS_BYTES + b_kb + kb;
                uint32_t bh[4], bl[4];
                LDMX4(bh, baddr);
                LDMX4(bl, baddr + ARR_B);
                #pragma unroll
                for (int mt = 0; mt < 4; mt++)
                    #pragma unroll
                    for (int nn = 0; nn < 2; nn++)
                        MMA16816(c[mt][n16 * 2 + nn], ah[mt], bh[2*nn], bh[2*nn+1]);
                #pragma unroll
                for (int mt = 0; mt < 4; mt++)
                    #pragma unroll
                    for (int nn = 0; nn < 2; nn++)
                        MMA16816(c[mt][n16 * 2 + nn], ah[mt], bl[2*nn], bl[2*nn+1]);
                #pragma unroll
                for (int mt = 0; mt < 4; mt++)
                    #pragma unroll
                    for (int nn = 0; nn < 2; nn++)
                        MMA16816(c[mt][n16 * 2 + nn], al[mt], bh[2*nn], bh[2*nn+1]);
            }
        }
        if (kt + 2 < NT)
            load_stage(sb + (uint32_t)((kt + 2) % NSTAGE) * STAGE_BYTES,
                       tid, Ah, Al, Bh, Bl, bm, bn, ldK, (kt + 2) * BK);
    }

    const int quad = lane >> 2;
    const int tq   = lane & 3;
    #pragma unroll
    for (int nt = 0; nt < 4; nt++) {
        const int col = bn + warpN * 32 + nt * 8 + tq * 2;
        float bv0 = bias[col], bv1 = bias[col + 1];
        #pragma unroll
        for (int mt = 0; mt < 4; mt++) {
            #pragma unroll
            for (int half = 0; half < 2; half++) {
                const int grow = bm + warpM * 64 + mt * 16 + half * 8 + quad;
                const size_t off = ((size_t)grow * row_mul + row_off) * N + col;
                float v0 = c[mt][nt][2 * half + 0] + bv0;
                float v1 = c[mt][nt][2 * half + 1] + bv1;
                __nv_bfloat16 h0 = __float2bfloat16(v0);
                __nv_bfloat16 h1 = __float2bfloat16(v1);
                __nv_bfloat162 hp; hp.x = h0; hp.y = h1;
                *(__nv_bfloat162*)(outH + off) = hp;
                __nv_bfloat162 lp;
                lp.x = __float2bfloat16(v0 - __bfloat162float(h0));
                lp.y = __float2bfloat16(v1 - __bfloat162float(h1));
                *(__nv_bfloat162*)(outL + off) = lp;
                uint2 tv;
                tv.x = cvt_tf32(v0);
                tv.y = cvt_tf32(v1);
                *(uint2*)((uint32_t*)outT + off) = tv;
            }
        }
    }
}

// merged f1/f2 projection: blockIdx.z = modality
__global__ void __launch_bounds__(512, 1)
gemm_proj(const __nv_bfloat16* __restrict__ f1h, const __nv_bfloat16* __restrict__ f1l,
          const __nv_bfloat16* __restrict__ w1h, const __nv_bfloat16* __restrict__ w1l,
          const float* __restrict__ b1,
          const __nv_bfloat16* __restrict__ f2h, const __nv_bfloat16* __restrict__ f2l,
          const __nv_bfloat16* __restrict__ w2h, const __nv_bfloat16* __restrict__ w2l,
          const float* __restrict__ b2,
          __nv_bfloat16* __restrict__ xh, __nv_bfloat16* __restrict__ xl,
          float* __restrict__ xt)
{
    extern __shared__ char smem[];
    if (blockIdx.z == 0)
        gemm_body(f1h, f1l, w1h, w1l, b1, xh, xl, xt,
                  HDIM, IMGDIM, 2, 0, blockIdx.y * BM, blockIdx.x * BN,
                  smem_u32(smem));
    else
        gemm_body(f2h, f2l, w2h, w2l, b2, xh, xl, xt,
                  HDIM, QDIM, 2, 1, blockIdx.y * BM, blockIdx.x * BN,
                  smem_u32(smem));
}

// ================= tf32 single-term path (G3 / G4) ==============================
__device__ __forceinline__ void load_stage_t(
    uint32_t st, int tid, const float* __restrict__ A,
    const float* __restrict__ B, int bm, int bn, int ldK, int k0)
{
    const int q  = tid & 7;      // 16B chunk (4 floats) within 128B row
    const int rb = tid >> 3;     // 0..63
    #pragma unroll
    for (int t = 0; t < 6; t++) {
        const float* g;
        uint32_t sa;
        if (t < 4) {
            const int r = t * 64 + rb;                 // 0..255
            g  = A + (size_t)(bm + r) * ldK + k0 + q * 4;
            sa = st + T_OFF_A + (uint32_t)r * KT_BYTES + q * 16;
        } else {
            const int r = (t - 4) * 64 + rb;           // 0..127
            g  = B + (size_t)(bn + r) * ldK + k0 + q * 4;
            sa = st + T_OFF_B + (uint32_t)r * KT_BYTES + q * 16;
        }
        cp16(sa, g);
    }
    asm volatile("cp.async.commit_group;" ::: "memory");
}

// gridDim.z = 1: full-K -> out0.  gridDim.z = 2: split-K halves -> out0/out1.
__global__ void __launch_bounds__(512, 1)
gemm_tf32(const float* __restrict__ A, const float* __restrict__ B,
          float* __restrict__ out0, float* __restrict__ out1,
          int N, int ldK)
{
    extern __shared__ char smem[];
    const uint32_t sb = smem_u32(smem);
    const int klen = ldK / gridDim.z;
    const float* Ab = A + blockIdx.z * klen;
    const float* Bb = B + blockIdx.z * klen;
    float* outF = blockIdx.z ? out1 : out0;

    const int tid   = threadIdx.x;
    const int wid   = tid >> 5;
    const int lane  = tid & 31;
    const int warpM = wid >> 2;      // 0..3 -> 64 rows
    const int warpN = wid & 3;       // 0..3 -> 32 cols
    const int bm = blockIdx.y * BM;
    const int bn = blockIdx.x * BN;

    float c[4][4][4];
    #pragma unroll
    for (int i = 0; i < 4; i++)
        #pragma unroll
        for (int j = 0; j < 4; j++)
            #pragma unroll
            for (int k = 0; k < 4; k++) c[i][j][k] = 0.0f;

    const int NT = klen / BK;
    load_stage_t(sb,           tid, Ab, Bb, bm, bn, ldK, 0);
    load_stage_t(sb + T_STAGE, tid, Ab, Bb, bm, bn, ldK, BK);

    const int g4 = lane >> 2;    // 0..7
    const int l4 = lane & 3;     // 0..3
    const uint32_t a_base = (uint32_t)(warpM * 64 + g4) * KT_BYTES + l4 * 4;
    const uint32_t b_base = (uint32_t)(warpN * 32 + g4) * KT_BYTES + l4 * 4;

    for (int kt = 0; kt < NT; kt++) {
        if (kt + 1 < NT) asm volatile("cp.async.wait_group 1;" ::: "memory");
        else             asm volatile("cp.async.wait_group 0;" ::: "memory");
        __syncthreads();

        const uint32_t st = sb + (uint32_t)(kt % NSTAGE) * T_STAGE;
        #pragma unroll
        for (int k8 = 0; k8 < 4; k8++) {
            const uint32_t kb = (uint32_t)k8 * 32;   // 8 floats
            uint32_t a[4][4];
            #pragma unroll
            for (int mt = 0; mt < 4; mt++) {
                const uint32_t r0 = st + T_OFF_A + a_base +
                                    (uint32_t)(mt * 16) * KT_BYTES + kb;
                LDS32(a[mt][0], r0);
                LDS32(a[mt][1], r0 + 8 * KT_BYTES);
                LDS32(a[mt][2], r0 + 16);
                LDS32(a[mt][3], r0 + 8 * KT_BYTES + 16);
            }
            #pragma unroll
            for (int n8 = 0; n8 < 4; n8++) {
                const uint32_t rb0 = st + T_OFF_B + b_base +
                                     (uint32_t)(n8 * 8) * KT_BYTES + kb;
                uint32_t b0, b1;
                LDS32(b0, rb0);
                LDS32(b1, rb0 + 16);
                #pragma unroll
                for (int mt = 0; mt < 4; mt++)
                    MMATF32(c[mt][n8], a[mt], b0, b1);
            }
        }
        if (kt + 2 < NT)
            load_stage_t(sb + (uint32_t)((kt + 2) % NSTAGE) * T_STAGE,
                         tid, Ab, Bb, bm, bn, ldK, (kt + 2) * BK);
    }

    // ---- epilogue: fp32 stores ----
    const int quad = lane >> 2;
    const int tq   = lane & 3;
    #pragma unroll
    for (int nt = 0; nt < 4; nt++) {
        const int col = bn + warpN * 32 + nt * 8 + tq * 2;
        #pragma unroll
        for (int mt = 0; mt < 4; mt++) {
            #pragma unroll
            for (int half = 0; half < 2; half++) {
                const int grow = bm + warpM * 64 + mt * 16 + half * 8 + quad;
                const size_t off = (size_t)grow * N + col;
                *(float2*)(outF + off) =
                    make_float2(c[mt][nt][2 * half + 0], c[mt][nt][2 * half + 1]);
            }
        }
    }
}

// ---------------- elementwise split (both features, one launch) ----------------
__global__ void __launch_bounds__(256)
asplit_all(const float* __restrict__ x1, __nv_bfloat16* __restrict__ h1,
           __nv_bfloat16* __restrict__ l1,
           const float* __restrict__ x2, __nv_bfloat16* __restrict__ h2,
           __nv_bfloat16* __restrict__ l2)
{
    const float* x; __nv_bfloat16 *h, *l; size_t n;
    if (blockIdx.z == 0) { x = x1; h = h1; l = l1; n = (size_t)BATCH * IMGDIM; }
    else                 { x = x2; h = h2; l = l2; n = (size_t)BATCH * QDIM; }
    size_t i = ((size_t)blockIdx.x * 256 + threadIdx.x) * 4;
    if (i >= n) return;
    float4 v = *(const float4*)(x + i);
    __nv_bfloat16 h0 = __float2bfloat16(v.x), hb1 = __float2bfloat16(v.y);
    __nv_bfloat16 h2b = __float2bfloat16(v.z), h3 = __float2bfloat16(v.w);
    __nv_bfloat162 hp0; hp0.x = h0;  hp0.y = hb1;
    __nv_bfloat162 hp1; hp1.x = h2b; hp1.y = h3;
    *(__nv_bfloat162*)(h + i)     = hp0;
    *(__nv_bfloat162*)(h + i + 2) = hp1;
    __nv_bfloat162 lp0, lp1;
    lp0.x = __float2bfloat16(v.x - __bfloat162float(h0));
    lp0.y = __float2bfloat16(v.y - __bfloat162float(hb1));
    lp1.x = __float2bfloat16(v.z - __bfloat162float(h2b));
    lp1.y = __float2bfloat16(v.w - __bfloat162float(h3));
    *(__nv_bfloat162*)(l + i)     = lp0;
    *(__nv_bfloat162*)(l + i + 2) = lp1;
}

// ---------------- weight transpose: z<2 bf16 hi/lo, z>=2 tf32 fp32 -------------
__global__ void __launch_bounds__(256)
wsplit_v3(const float* __restrict__ W1, const float* __restrict__ W2,
          const float* __restrict__ Wq, const float* __restrict__ Wo,
          __nv_bfloat16* __restrict__ w1h, __nv_bfloat16* __restrict__ w1l,
          __nv_bfloat16* __restrict__ w2h, __nv_bfloat16* __restrict__ w2l,
          float* __restrict__ wqt, float* __restrict__ wot)
{
    const float* W; __nv_bfloat16 *th = nullptr, *tl = nullptr;
    float* tt = nullptr; int K, N;
    switch (blockIdx.z) {
        case 0: W = W1; th = w1h; tl = w1l; K = IMGDIM; N = HDIM; break;
        case 1: W = W2; th = w2h; tl = w2l; K = QDIM;   N = HDIM; break;
        case 2: W = Wq; tt = wqt;           K = HDIM;   N = H3;   break;
        default:W = Wo; tt = wot;           K = HDIM;   N = HDIM; break;
    }
    const int n0 = blockIdx.x * 32, k0 = blockIdx.y * 64;
    if (n0 >= N || k0 >= K) return;

    __shared__ float tile[64][33];
    const int tx = threadIdx.x & 31, ty = threadIdx.x >> 5;
    #pragma unroll
    for (int i = ty; i < 64; i += 8)
        tile[i][tx] = W[(size_t)(k0 + i) * N + n0 + tx];
    __syncthreads();
    #pragma unroll
    for (int i = 0; i < 4; i++) {
        const int nn = ty + i * 8;
        const int n = n0 + nn;
        float v0 = tile[2 * tx + 0][nn];
        float v1 = tile[2 * tx + 1][nn];
        const size_t off = (size_t)n * K + k0 + 2 * tx;
        if (tt) {
            uint2 tv; tv.x = cvt_tf32(v0); tv.y = cvt_tf32(v1);
            *(uint2*)((uint32_t*)tt + off) = tv;
        } else {
            __nv_bfloat16 h0 = __float2bfloat16(v0);
            __nv_bfloat16 h1 = __float2bfloat16(v1);
            __nv_bfloat162 hp; hp.x = h0; hp.y = h1;
            __nv_bfloat162 lp;
            lp.x = __float2bfloat16(v0 - __bfloat162float(h0));
            lp.y = __float2bfloat16(v1 - __bfloat162float(h1));
            *(__nv_bfloat162*)(th + off) = hp;
            *(__nv_bfloat162*)(tl + off) = lp;
        }
    }
}

// ---------------- attention: out = tf32-rounded fp32 ---------------------------
__global__ void __launch_bounds__(128)
attn_kernel(const float* __restrict__ qkv, float* __restrict__ att)
{
    const int b = blockIdx.x;
    const int warp = threadIdx.x >> 5;
    const int lane = threadIdx.x & 31;
    const float scale = 0.125f;
    const size_t base0 = (size_t)(2 * b) * H3;
    const size_t base1 = base0 + H3;

    #pragma unroll
    for (int h = warp; h < NHEADS; h += 4) {
        const int off = h * HD + lane;
        float q0a = qkv[base0 + off],          q0b = qkv[base0 + off + 32];
        float k0a = qkv[base0 + HDIM + off],   k0b = qkv[base0 + HDIM + off + 32];
        float v0a = qkv[base0 + 2*HDIM + off], v0b = qkv[base0 + 2*HDIM + off + 32];
        float q1a = qkv[base1 + off],          q1b = qkv[base1 + off + 32];
        float k1a = qkv[base1 + HDIM + off],   k1b = qkv[base1 + HDIM + off + 32];
        float v1a = qkv[base1 + 2*HDIM + off], v1b = qkv[base1 + 2*HDIM + off + 32];

        float s00 = q0a * k0a + q0b * k0b;
        float s01 = q0a * k1a + q0b * k1b;
        float s10 = q1a * k0a + q1b * k0b;
        float s11 = q1a * k1a + q1b * k1b;
        #pragma unroll
        for (int d = 16; d; d >>= 1) {
            s00 += __shfl_xor_sync(0xffffffffu, s00, d);
            s01 += __shfl_xor_sync(0xffffffffu, s01, d);
            s10 += __shfl_xor_sync(0xffffffffu, s10, d);
            s11 += __shfl_xor_sync(0xffffffffu, s11, d);
        }
        s00 *= scale; s01 *= scale; s10 *= scale; s11 *= scale;

        float m0 = fmaxf(s00, s01), m1 = fmaxf(s10, s11);
        float e00 = __expf(s00 - m0), e01 = __expf(s01 - m0);
        float e10 = __expf(s10 - m1), e11 = __expf(s11 - m1);
        float inv0 = 1.0f / (e00 + e01), inv1 = 1.0f / (e10 + e11);
        float p00 = e00 * inv0, p01 = e01 * inv0;
        float p10 = e10 * inv1, p11 = e11 * inv1;

        float r0 = p00 * v0a + p01 * v1a;
        float r1 = p00 * v0b + p01 * v1b;
        float r2 = p10 * v0a + p11 * v1a;
        float r3 = p10 * v0b + p11 * v1b;

        size_t o0 = (size_t)(2 * b) * HDIM + h * HD + lane;
        size_t o1 = o0 + HDIM;
        uint32_t* a32 = (uint32_t*)att;
        a32[o0]      = cvt_tf32(r0);
        a32[o0 + 32] = cvt_tf32(r1);
        a32[o1]      = cvt_tf32(r2);
        a32[o1 + 32] = cvt_tf32(r3);
    }
}

// ---------------- LayerNorm: sums split-K halves + bias + residual(hi+lo) ------
__global__ void __launch_bounds__(256)
ln_kernel(const float* __restrict__ o2a, const float* __restrict__ o2b,
          const float* __restrict__ bout,
          const __nv_bfloat16* __restrict__ xh, const __nv_bfloat16* __restrict__ xl,
          const float* __restrict__ gamma, const float* __restrict__ beta,
          float* __restrict__ out)
{
    const int b = blockIdx.x;
    const int tid = threadIdx.x;
    const float4* xa4 = (const float4*)(o2a + (size_t)b * 2048);
    const float4* xb4 = (const float4*)(o2b + (size_t)b * 2048);
    const float4* bo4 = (const float4*)bout;
    const float4 bv = bo4[tid];

    float4 vals[2];
    float sum = 0.0f, sq = 0.0f;
    #pragma unroll
    for (int j = 0; j < 2; j++) {
        const int c4 = tid + j * 256;
        float4 a = xa4[c4], bb = xb4[c4];
        float4 v;
        v.x = a.x + bb.x + bv.x;
        v.y = a.y + bb.y + bv.y;
        v.z = a.z + bb.z + bv.z;
        v.w = a.w + bb.w + bv.w;
        vals[j] = v;
        sum += v.x + v.y + v.z + v.w;
        sq  += v.x * v.x + v.y * v.y + v.z * v.z + v.w * v.w;
    }
    #pragma unroll
    for (int d = 16; d; d >>= 1) {
        sum += __shfl_xor_sync(0xffffffffu, sum, d);
        sq  += __shfl_xor_sync(0xffffffffu, sq, d);
    }
    __shared__ float ssum[8], ssq[8];
    const int warp = tid >> 5, lane = tid & 31;
    if (lane == 0) { ssum[warp] = sum; ssq[warp] = sq; }
    __syncthreads();
    float tsum = 0.0f, tsq = 0.0f;
    #pragma unroll
    for (int w = 0; w < 8; w++) { tsum += ssum[w]; tsq += ssq[w]; }

    const float mu   = tsum * (1.0f / 2048.0f);
    const float var  = tsq * (1.0f / 2048.0f) - mu * mu;
    const float rinv = rsqrtf(var + 1e-5f);

    const __nv_bfloat162* rh2 = (const __nv_bfloat162*)(xh + (size_t)b * 2048);
    const __nv_bfloat162* rl2 = (const __nv_bfloat162*)(xl + (size_t)b * 2048);
    const float4* g4 = (const float4*)gamma;
    const float4* bt4 = (const float4*)beta;
    float4* o4 = (float4*)(out + (size_t)b * 2048);
    #pragma unroll
    for (int j = 0; j < 2; j++) {
        const int c4 = tid + j * 256;
        float4 g = g4[c4], bt = bt4[c4];
        __nv_bfloat162 rh0 = rh2[2 * c4], rh1 = rh2[2 * c4 + 1];
        __nv_bfloat162 rl0 = rl2[2 * c4], rl1 = rl2[2 * c4 + 1];
        float4 v = vals[j];
        float4 o;
        o.x = (v.x - mu) * rinv * g.x + bt.x +
              __bfloat162float(rh0.x) + __bfloat162float(rl0.x);
        o.y = (v.y - mu) * rinv * g.y + bt.y +
              __bfloat162float(rh0.y) + __bfloat162float(rl0.y);
        o.z = (v.z - mu) * rinv * g.z + bt.z +
              __bfloat162float(rh1.x) + __bfloat162float(rl1.x);
        o.w = (v.w - mu) * rinv * g.w + bt.w +
              __bfloat162float(rh1.y) + __bfloat162float(rl1.y);
        o4[c4] = o;
    }
}

// ---------------------------------------------------------------------------
extern "C" void kernel_launch(void* const* d_in, const int* in_sizes, int n_in,
                              void* d_out, int out_size)
{
    const float* features1 = (const float*)d_in[0];
    const float* features2 = (const float*)d_in[1];
    const float* W1    = (const float*)d_in[2];
    const float* b1    = (const float*)d_in[3];
    const float* W2    = (const float*)d_in[4];
    const float* b2    = (const float*)d_in[5];
    const float* Wqkv  = (const float*)d_in[6];
    const float* Wout  = (const float*)d_in[7];
    const float* bout  = (const float*)d_in[8];
    const float* gamma = (const float*)d_in[9];
    const float* beta  = (const float*)d_in[10];
    float* out = (float*)d_out;

    float *p_qkv, *p_o2a, *p_o2b, *p_xt, *p_att, *p_wqt, *p_wot;
    __nv_bfloat16 *p_f1h, *p_f1l, *p_f2h, *p_f2l, *p_xh, *p_xl;
    __nv_bfloat16 *p_w1h, *p_w1l, *p_w2h, *p_w2l;
    cudaGetSymbolAddress((void**)&p_qkv, g_qkv);
    cudaGetSymbolAddress((void**)&p_o2a, g_o2a);
    cudaGetSymbolAddress((void**)&p_o2b, g_o2b);
    cudaGetSymbolAddress((void**)&p_xt,  g_xt);
    cudaGetSymbolAddress((void**)&p_att, g_att);
    cudaGetSymbolAddress((void**)&p_wqt, g_wqt);
    cudaGetSymbolAddress((void**)&p_wot, g_wot);
    cudaGetSymbolAddress((void**)&p_f1h, g_f1h); cudaGetSymbolAddress((void**)&p_f1l, g_f1l);
    cudaGetSymbolAddress((void**)&p_f2h, g_f2h); cudaGetSymbolAddress((void**)&p_f2l, g_f2l);
    cudaGetSymbolAddress((void**)&p_xh,  g_xh);  cudaGetSymbolAddress((void**)&p_xl,  g_xl);
    cudaGetSymbolAddress((void**)&p_w1h, g_w1h); cudaGetSymbolAddress((void**)&p_w1l, g_w1l);
    cudaGetSymbolAddress((void**)&p_w2h, g_w2h); cudaGetSymbolAddress((void**)&p_w2l, g_w2l);

    cudaFuncSetAttribute(gemm_proj, cudaFuncAttributeMaxDynamicSharedMemorySize,
                         SMEM_BYTES);
    cudaFuncSetAttribute(gemm_tf32, cudaFuncAttributeMaxDynamicSharedMemorySize,
                         T_SMEM);

    // ncu (-s 5 -c 1) captures our 4th launch -> G3 (tf32 qkv GEMM).
    asplit_all<<<dim3((BATCH * IMGDIM + 1023) / 1024, 1, 2), 256>>>(
        features1, p_f1h, p_f1l, features2, p_f2h, p_f2l);                        // 1
    wsplit_v3<<<dim3(H3 / 32, IMGDIM / 64, 4), 256>>>(
        W1, W2, Wqkv, Wout, p_w1h, p_w1l, p_w2h, p_w2l, p_wqt, p_wot);            // 2
    gemm_proj<<<dim3(HDIM / BN, BATCH / BM, 2), 512, SMEM_BYTES>>>(
        p_f1h, p_f1l, p_w1h, p_w1l, b1,
        p_f2h, p_f2l, p_w2h, p_w2l, b2, p_xh, p_xl, p_xt);                        // 3
    // G3: x @ Wqkv (single-term tf32) -> qkv fp32 (profiled launch)
    gemm_tf32<<<dim3(H3 / BN, B2 / BM, 1), 512, T_SMEM>>>(
        p_xt, p_wqt, p_qkv, nullptr, H3, HDIM);                                   // 4
    attn_kernel<<<BATCH, 128>>>(p_qkv, p_att);                                    // 5
    // G4: att @ Wout (tf32, split-K=2) -> o2a + o2b (bias folded into LN)
    gemm_tf32<<<dim3(HDIM / BN, B2 / BM, 2), 512, T_SMEM>>>(
        p_att, p_wot, p_o2a, p_o2b, HDIM, HDIM);                                  // 6
    ln_kernel<<<BATCH, 256>>>(p_o2a, p_o2b, bout, p_xh, p_xl, gamma, beta, out);  // 7

    (void)in_sizes; (void)n_in; (void)out_size;
}

// round 17
// speedup vs baseline: 1.7169x; 1.0748x over previous
#include <cuda_runtime.h>
#include <cuda_bf16.h>
#include <stdint.h>
#include <math.h>

// ---------------------------------------------------------------------------
// MultiModalAttention (sm_103 base target).
// Round 17: FULL single-term tf32 pipeline. All four GEMMs use m16n8k8 tf32
// with RNE-rounded operands. Proj stores exact fp32 x (residual) + rounded xt
// (G3 operand). G4 keeps split-K=2 with the reduction fused into LayerNorm.
// ---------------------------------------------------------------------------

#define BATCH   8192
#define IMGDIM  2048
#define QDIM    768
#define HDIM    1024
#define H3      3072
#define B2      16384
#define NHEADS  16
#define HD      64

#define BM 256
#define BN 128
#define BK 32
#define NSTAGE 3
// tf32 tiling
#define KT_BYTES 144                          // 32 f32 = 128B + 16 pad
#define T_ARR_A (BM * KT_BYTES)               // 36864
#define T_ARR_B (BN * KT_BYTES)               // 18432
#define T_OFF_A 0
#define T_OFF_B (T_ARR_A)
#define T_STAGE (T_ARR_A + T_ARR_B)           // 55296
#define T_SMEM  (NSTAGE * T_STAGE)            // 165888

// ---------------- device scratch ---------------------------------------------
__device__ float g_qkv[(size_t)B2 * H3];
__device__ float g_o2a[(size_t)B2 * HDIM];
__device__ float g_o2b[(size_t)B2 * HDIM];
__device__ float g_x  [(size_t)B2 * HDIM];    // exact fp32 x (residual)
__device__ float g_xt [(size_t)B2 * HDIM];    // tf32-rounded x (G3 A)
__device__ float g_att[(size_t)B2 * HDIM];    // tf32-rounded attention out
__device__ float g_f1t[(size_t)BATCH * IMGDIM];
__device__ float g_f2t[(size_t)BATCH * QDIM];
__device__ float g_w1t[(size_t)HDIM * IMGDIM];
__device__ float g_w2t[(size_t)HDIM * QDIM];
__device__ float g_wqt[(size_t)H3 * HDIM];
__device__ float g_wot[(size_t)HDIM * HDIM];

// ---------------- helpers ------------------------------------------------------
__device__ __forceinline__ uint32_t smem_u32(const void* p) {
    return (uint32_t)__cvta_generic_to_shared(p);
}
__device__ __forceinline__ void cp16(uint32_t s, const void* g) {
    asm volatile("cp.async.cg.shared.global [%0], [%1], 16;"
                 :: "r"(s), "l"(__cvta_generic_to_global(g)) : "memory");
}
// round-to-nearest-even onto the tf32 (2^13) boundary; unbiased.
__device__ __forceinline__ uint32_t cvt_tf32(float f) {
    uint32_t x = __float_as_uint(f);
    return (x + 0xFFFu + ((x >> 13) & 1u)) & ~0x1FFFu;
}
#define MMATF32(c, a, b0, b1) \
    asm volatile("mma.sync.aligned.m16n8k8.row.col.f32.tf32.tf32.f32 " \
        "{%0,%1,%2,%3}, {%4,%5,%6,%7}, {%8,%9}, {%0,%1,%2,%3};" \
        : "+f"((c)[0]), "+f"((c)[1]), "+f"((c)[2]), "+f"((c)[3]) \
        : "r"((a)[0]), "r"((a)[1]), "r"((a)[2]), "r"((a)[3]), "r"(b0), "r"(b1))
#define LDS32(r, addr) \
    asm volatile("ld.shared.b32 %0, [%1];" : "=r"(r) : "r"(addr))

// ---------------- tf32 stage loader (512 threads, 6 cp.async each) -------------
__device__ __forceinline__ void load_stage_t(
    uint32_t st, int tid, const float* __restrict__ A,
    const float* __restrict__ B, int bm, int bn, int ldK, int k0)
{
    const int q  = tid & 7;
    const int rb = tid >> 3;     // 0..63
    #pragma unroll
    for (int t = 0; t < 6; t++) {
        const float* g;
        uint32_t sa;
        if (t < 4) {
            const int r = t * 64 + rb;                 // 0..255
            g  = A + (size_t)(bm + r) * ldK + k0 + q * 4;
            sa = st + T_OFF_A + (uint32_t)r * KT_BYTES + q * 16;
        } else {
            const int r = (t - 4) * 64 + rb;           // 0..127
            g  = B + (size_t)(bn + r) * ldK + k0 + q * 4;
            sa = st + T_OFF_B + (uint32_t)r * KT_BYTES + q * 16;
        }
        cp16(sa, g);
    }
    asm volatile("cp.async.commit_group;" ::: "memory");
}

// ---------------- shared tf32 GEMM body -----------------------------------------
// out0: fp32 (exact accumulation); outT: optional tf32-rounded copy of out0.
__device__ __forceinline__ void gemm_tf32_body(
    const float* __restrict__ A, const float* __restrict__ B,
    const float* __restrict__ bias,
    float* __restrict__ out0, float* __restrict__ outT,
    int N, int ldK, int klen, int row_mul, int row_off, int bm, int bn,
    uint32_t sb)
{
    const int tid   = threadIdx.x;
    const int wid   = tid >> 5;
    const int lane  = tid & 31;
    const int warpM = wid >> 2;      // 0..3 -> 64 rows
    const int warpN = wid & 3;       // 0..3 -> 32 cols
    float c[4][4][4];
    #pragma unroll
    for (int i = 0; i < 4; i++)
        #pragma unroll
        for (int j = 0; j < 4; j++)
            #pragma unroll
            for (int k = 0; k < 4; k++) c[i][j][k] = 0.0f;

    const int NT = klen / BK;
    load_stage_t(sb,           tid, A, B, bm, bn, ldK, 0);
    load_stage_t(sb + T_STAGE, tid, A, B, bm, bn, ldK, BK);

    const int g4 = lane >> 2;
    const int l4 = lane & 3;
    const uint32_t a_base = (uint32_t)(warpM * 64 + g4) * KT_BYTES + l4 * 4;
    const uint32_t b_base = (uint32_t)(warpN * 32 + g4) * KT_BYTES + l4 * 4;

    for (int kt = 0; kt < NT; kt++) {
        if (kt + 1 < NT) asm volatile("cp.async.wait_group 1;" ::: "memory");
        else             asm volatile("cp.async.wait_group 0;" ::: "memory");
        __syncthreads();

        const uint32_t st = sb + (uint32_t)(kt % NSTAGE) * T_STAGE;
        #pragma unroll
        for (int k8 = 0; k8 < 4; k8++) {
            const uint32_t kb = (uint32_t)k8 * 32;
            uint32_t a[4][4];
            #pragma unroll
            for (int mt = 0; mt < 4; mt++) {
                const uint32_t r0 = st + T_OFF_A + a_base +
                                    (uint32_t)(mt * 16) * KT_BYTES + kb;
                LDS32(a[mt][0], r0);
                LDS32(a[mt][1], r0 + 8 * KT_BYTES);
                LDS32(a[mt][2], r0 + 16);
                LDS32(a[mt][3], r0 + 8 * KT_BYTES + 16);
            }
            #pragma unroll
            for (int n8 = 0; n8 < 4; n8++) {
                const uint32_t rb0 = st + T_OFF_B + b_base +
                                     (uint32_t)(n8 * 8) * KT_BYTES + kb;
                uint32_t b0, b1;
                LDS32(b0, rb0);
                LDS32(b1, rb0 + 16);
                #pragma unroll
                for (int mt = 0; mt < 4; mt++)
                    MMATF32(c[mt][n8], a[mt], b0, b1);
            }
        }
        if (kt + 2 < NT)
            load_stage_t(sb + (uint32_t)((kt + 2) % NSTAGE) * T_STAGE,
                         tid, A, B, bm, bn, ldK, (kt + 2) * BK);
    }

    const int quad = lane >> 2;
    const int tq   = lane & 3;
    #pragma unroll
    for (int nt = 0; nt < 4; nt++) {
        const int col = bn + warpN * 32 + nt * 8 + tq * 2;
        float bv0 = 0.0f, bv1 = 0.0f;
        if (bias) { bv0 = bias[col]; bv1 = bias[col + 1]; }
        #pragma unroll
        for (int mt = 0; mt < 4; mt++) {
            #pragma unroll
            for (int half = 0; half < 2; half++) {
                const int grow = bm + warpM * 64 + mt * 16 + half * 8 + quad;
                const size_t off = ((size_t)grow * row_mul + row_off) * N + col;
                float v0 = c[mt][nt][2 * half + 0] + bv0;
                float v1 = c[mt][nt][2 * half + 1] + bv1;
                *(float2*)(out0 + off) = make_float2(v0, v1);
                if (outT) {
                    uint2 tv; tv.x = cvt_tf32(v0); tv.y = cvt_tf32(v1);
                    *(uint2*)((uint32_t*)outT + off) = tv;
                }
            }
        }
    }
}

// ---------------- GEMM kernels -------------------------------------------------
// gridDim.z = 1: full-K -> out0. gridDim.z = 2: split-K halves -> out0/out1.
__global__ void __launch_bounds__(512, 1)
gemm_tf32(const float* __restrict__ A, const float* __restrict__ B,
          float* __restrict__ out0, float* __restrict__ out1,
          int N, int ldK)
{
    extern __shared__ char smem[];
    const int klen = ldK / gridDim.z;
    gemm_tf32_body(A + blockIdx.z * klen, B + blockIdx.z * klen, nullptr,
                   blockIdx.z ? out1 : out0, nullptr,
                   N, ldK, klen, 1, 0, blockIdx.y * BM, blockIdx.x * BN,
                   smem_u32(smem));
}

// merged f1/f2 projection (tf32): x fp32 (residual) + xt rounded (G3 operand)
__global__ void __launch_bounds__(512, 1)
gemm_proj(const float* __restrict__ f1t, const float* __restrict__ w1t,
          const float* __restrict__ b1,
          const float* __restrict__ f2t, const float* __restrict__ w2t,
          const float* __restrict__ b2,
          float* __restrict__ x, float* __restrict__ xt)
{
    extern __shared__ char smem[];
    if (blockIdx.z == 0)
        gemm_tf32_body(f1t, w1t, b1, x, xt, HDIM, IMGDIM, IMGDIM, 2, 0,
                       blockIdx.y * BM, blockIdx.x * BN, smem_u32(smem));
    else
        gemm_tf32_body(f2t, w2t, b2, x, xt, HDIM, QDIM, QDIM, 2, 1,
                       blockIdx.y * BM, blockIdx.x * BN, smem_u32(smem));
}

// ---------------- feature rounding (both modalities, one launch) ---------------
__global__ void __launch_bounds__(256)
asplit_all(const float* __restrict__ x1, float* __restrict__ t1,
           const float* __restrict__ x2, float* __restrict__ t2)
{
    const float* x; float* t; size_t n;
    if (blockIdx.z == 0) { x = x1; t = t1; n = (size_t)BATCH * IMGDIM; }
    else                 { x = x2; t = t2; n = (size_t)BATCH * QDIM; }
    size_t i = ((size_t)blockIdx.x * 256 + threadIdx.x) * 4;
    if (i >= n) return;
    float4 v = *(const float4*)(x + i);
    uint4 o;
    o.x = cvt_tf32(v.x); o.y = cvt_tf32(v.y);
    o.z = cvt_tf32(v.z); o.w = cvt_tf32(v.w);
    *(uint4*)((uint32_t*)t + i) = o;
}

// ---------------- weight transpose + tf32 round (all 4, one launch) ------------
__global__ void __launch_bounds__(256)
wsplit_t(const float* __restrict__ W1, const float* __restrict__ W2,
         const float* __restrict__ Wq, const float* __restrict__ Wo,
         float* __restrict__ w1t, float* __restrict__ w2t,
         float* __restrict__ wqt, float* __restrict__ wot)
{
    const float* W; float* tt; int K, N;
    switch (blockIdx.z) {
        case 0: W = W1; tt = w1t; K = IMGDIM; N = HDIM; break;
        case 1: W = W2; tt = w2t; K = QDIM;   N = HDIM; break;
        case 2: W = Wq; tt = wqt; K = HDIM;   N = H3;   break;
        default:W = Wo; tt = wot; K = HDIM;   N = HDIM; break;
    }
    const int n0 = blockIdx.x * 32, k0 = blockIdx.y * 64;
    if (n0 >= N || k0 >= K) return;

    __shared__ float tile[64][33];
    const int tx = threadIdx.x & 31, ty = threadIdx.x >> 5;
    #pragma unroll
    for (int i = ty; i < 64; i += 8)
        tile[i][tx] = W[(size_t)(k0 + i) * N + n0 + tx];
    __syncthreads();
    #pragma unroll
    for (int i = 0; i < 4; i++) {
        const int nn = ty + i * 8;
        const int n = n0 + nn;
        uint2 tv;
        tv.x = cvt_tf32(tile[2 * tx + 0][nn]);
        tv.y = cvt_tf32(tile[2 * tx + 1][nn]);
        *(uint2*)((uint32_t*)tt + (size_t)n * K + k0 + 2 * tx) = tv;
    }
}

// ---------------- attention: out = tf32-rounded fp32 ---------------------------
__global__ void __launch_bounds__(128)
attn_kernel(const float* __restrict__ qkv, float* __restrict__ att)
{
    const int b = blockIdx.x;
    const int warp = threadIdx.x >> 5;
    const int lane = threadIdx.x & 31;
    const float scale = 0.125f;
    const size_t base0 = (size_t)(2 * b) * H3;
    const size_t base1 = base0 + H3;

    #pragma unroll
    for (int h = warp; h < NHEADS; h += 4) {
        const int off = h * HD + lane;
        float q0a = qkv[base0 + off],          q0b = qkv[base0 + off + 32];
        float k0a = qkv[base0 + HDIM + off],   k0b = qkv[base0 + HDIM + off + 32];
        float v0a = qkv[base0 + 2*HDIM + off], v0b = qkv[base0 + 2*HDIM + off + 32];
        float q1a = qkv[base1 + off],          q1b = qkv[base1 + off + 32];
        float k1a = qkv[base1 + HDIM + off],   k1b = qkv[base1 + HDIM + off + 32];
        float v1a = qkv[base1 + 2*HDIM + off], v1b = qkv[base1 + 2*HDIM + off + 32];

        float s00 = q0a * k0a + q0b * k0b;
        float s01 = q0a * k1a + q0b * k1b;
        float s10 = q1a * k0a + q1b * k0b;
        float s11 = q1a * k1a + q1b * k1b;
        #pragma unroll
        for (int d = 16; d; d >>= 1) {
            s00 += __shfl_xor_sync(0xffffffffu, s00, d);
            s01 += __shfl_xor_sync(0xffffffffu, s01, d);
            s10 += __shfl_xor_sync(0xffffffffu, s10, d);
            s11 += __shfl_xor_sync(0xffffffffu, s11, d);
        }
        s00 *= scale; s01 *= scale; s10 *= scale; s11 *= scale;

        float m0 = fmaxf(s00, s01), m1 = fmaxf(s10, s11);
        float e00 = __expf(s00 - m0), e01 = __expf(s01 - m0);
        float e10 = __expf(s10 - m1), e11 = __expf(s11 - m1);
        float inv0 = 1.0f / (e00 + e01), inv1 = 1.0f / (e10 + e11);
        float p00 = e00 * inv0, p01 = e01 * inv0;
        float p10 = e10 * inv1, p11 = e11 * inv1;

        float r0 = p00 * v0a + p01 * v1a;
        float r1 = p00 * v0b + p01 * v1b;
        float r2 = p10 * v0a + p11 * v1a;
        float r3 = p10 * v0b + p11 * v1b;

        size_t o0 = (size_t)(2 * b) * HDIM + h * HD + lane;
        size_t o1 = o0 + HDIM;
        uint32_t* a32 = (uint32_t*)att;
        a32[o0]      = cvt_tf32(r0);
        a32[o0 + 32] = cvt_tf32(r1);
        a32[o1]      = cvt_tf32(r2);
        a32[o1 + 32] = cvt_tf32(r3);
    }
}

// ---------------- LayerNorm: split-K sum + bias + fp32 residual ----------------
__global__ void __launch_bounds__(256)
ln_kernel(const float* __restrict__ o2a, const float* __restrict__ o2b,
          const float* __restrict__ bout, const float* __restrict__ xres,
          const float* __restrict__ gamma, const float* __restrict__ beta,
          float* __restrict__ out)
{
    const int b = blockIdx.x;
    const int tid = threadIdx.x;
    const float4* xa4 = (const float4*)(o2a + (size_t)b * 2048);
    const float4* xb4 = (const float4*)(o2b + (size_t)b * 2048);
    const float4* bo4 = (const float4*)bout;
    const float4 bv = bo4[tid];

    float4 vals[2];
    float sum = 0.0f, sq = 0.0f;
    #pragma unroll
    for (int j = 0; j < 2; j++) {
        const int c4 = tid + j * 256;
        float4 a = xa4[c4], bb = xb4[c4];
        float4 v;
        v.x = a.x + bb.x + bv.x;
        v.y = a.y + bb.y + bv.y;
        v.z = a.z + bb.z + bv.z;
        v.w = a.w + bb.w + bv.w;
        vals[j] = v;
        sum += v.x + v.y + v.z + v.w;
        sq  += v.x * v.x + v.y * v.y + v.z * v.z + v.w * v.w;
    }
    #pragma unroll
    for (int d = 16; d; d >>= 1) {
        sum += __shfl_xor_sync(0xffffffffu, sum, d);
        sq  += __shfl_xor_sync(0xffffffffu, sq, d);
    }
    __shared__ float ssum[8], ssq[8];
    const int warp = tid >> 5, lane = tid & 31;
    if (lane == 0) { ssum[warp] = sum; ssq[warp] = sq; }
    __syncthreads();
    float tsum = 0.0f, tsq = 0.0f;
    #pragma unroll
    for (int w = 0; w < 8; w++) { tsum += ssum[w]; tsq += ssq[w]; }

    const float mu   = tsum * (1.0f / 2048.0f);
    const float var  = tsq * (1.0f / 2048.0f) - mu * mu;
    const float rinv = rsqrtf(var + 1e-5f);

    const float4* r4 = (const float4*)(xres + (size_t)b * 2048);
    const float4* g4 = (const float4*)gamma;
    const float4* bt4 = (const float4*)beta;
    float4* o4 = (float4*)(out + (size_t)b * 2048);
    #pragma unroll
    for (int j = 0; j < 2; j++) {
        const int c4 = tid + j * 256;
        float4 g = g4[c4], bt = bt4[c4], r = r4[c4];
        float4 v = vals[j];
        float4 o;
        o.x = (v.x - mu) * rinv * g.x + bt.x + r.x;
        o.y = (v.y - mu) * rinv * g.y + bt.y + r.y;
        o.z = (v.z - mu) * rinv * g.z + bt.z + r.z;
        o.w = (v.w - mu) * rinv * g.w + bt.w + r.w;
        o4[c4] = o;
    }
}

// ---------------------------------------------------------------------------
extern "C" void kernel_launch(void* const* d_in, const int* in_sizes, int n_in,
                              void* d_out, int out_size)
{
    const float* features1 = (const float*)d_in[0];
    const float* features2 = (const float*)d_in[1];
    const float* W1    = (const float*)d_in[2];
    const float* b1    = (const float*)d_in[3];
    const float* W2    = (const float*)d_in[4];
    const float* b2    = (const float*)d_in[5];
    const float* Wqkv  = (const float*)d_in[6];
    const float* Wout  = (const float*)d_in[7];
    const float* bout  = (const float*)d_in[8];
    const float* gamma = (const float*)d_in[9];
    const float* beta  = (const float*)d_in[10];
    float* out = (float*)d_out;

    float *p_qkv, *p_o2a, *p_o2b, *p_x, *p_xt, *p_att;
    float *p_f1t, *p_f2t, *p_w1t, *p_w2t, *p_wqt, *p_wot;
    cudaGetSymbolAddress((void**)&p_qkv, g_qkv);
    cudaGetSymbolAddress((void**)&p_o2a, g_o2a);
    cudaGetSymbolAddress((void**)&p_o2b, g_o2b);
    cudaGetSymbolAddress((void**)&p_x,   g_x);
    cudaGetSymbolAddress((void**)&p_xt,  g_xt);
    cudaGetSymbolAddress((void**)&p_att, g_att);
    cudaGetSymbolAddress((void**)&p_f1t, g_f1t);
    cudaGetSymbolAddress((void**)&p_f2t, g_f2t);
    cudaGetSymbolAddress((void**)&p_w1t, g_w1t);
    cudaGetSymbolAddress((void**)&p_w2t, g_w2t);
    cudaGetSymbolAddress((void**)&p_wqt, g_wqt);
    cudaGetSymbolAddress((void**)&p_wot, g_wot);

    cudaFuncSetAttribute(gemm_tf32, cudaFuncAttributeMaxDynamicSharedMemorySize,
                         T_SMEM);
    cudaFuncSetAttribute(gemm_proj, cudaFuncAttributeMaxDynamicSharedMemorySize,
                         T_SMEM);

    // ncu (-s 5 -c 1) captures our 4th launch -> G3 (tf32 qkv GEMM).
    asplit_all<<<dim3((BATCH * IMGDIM + 1023) / 1024, 1, 2), 256>>>(
        features1, p_f1t, features2, p_f2t);                                      // 1
    wsplit_t<<<dim3(H3 / 32, IMGDIM / 64, 4), 256>>>(
        W1, W2, Wqkv, Wout, p_w1t, p_w2t, p_wqt, p_wot);                          // 2
    gemm_proj<<<dim3(HDIM / BN, BATCH / BM, 2), 512, T_SMEM>>>(
        p_f1t, p_w1t, b1, p_f2t, p_w2t, b2, p_x, p_xt);                           // 3
    // G3: x @ Wqkv (tf32) -> qkv fp32 (profiled launch)
    gemm_tf32<<<dim3(H3 / BN, B2 / BM, 1), 512, T_SMEM>>>(
        p_xt, p_wqt, p_qkv, nullptr, H3, HDIM);                                   // 4
    attn_kernel<<<BATCH, 128>>>(p_qkv, p_att);                                    // 5
    // G4: att @ Wout (tf32, split-K=2) -> o2a + o2b (bias folded into LN)
    gemm_tf32<<<dim3(HDIM / BN, B2 / BM, 2), 512, T_SMEM>>>(
        p_att, p_wot, p_o2a, p_o2b, HDIM, HDIM);                                  // 6
    ln_kernel<<<BATCH, 256>>>(p_o2a, p_o2b, bout, p_x, gamma, beta, out);         // 7

    (void)in_sizes; (void)n_in; (void)out_size;
}